// round 12
// baseline (speedup 1.0000x reference)
#include <cuda_runtime.h>
#include <cuda.h>
#include <math.h>

#define BATCH   2
#define SEQ     4608
#define DIM     3584
#define NHD     8
#define DHD     448
#define NPATCH  4096
#define NBOX    12
#define DFF     7168
#define NTOK    24
#define TPB     256
#define TPBS    128

#define STG     5760        // floats per stage (big mma)
#define SMEM_BYTES (3 * STG * 4)
#define SSTG    3456        // floats per stage (skinny cp.async mma)
#define TMA_STAGE 12288
#define TMA_SMEM  (4 * TMA_STAGE)

// ------------------------- scratch ------------------------------------------
__device__ int   g_pos[NTOK];
__device__ int   g_start[BATCH];
__device__ float g_qtok[NTOK * DIM];
__device__ float g_q[NTOK * DIM];
__device__ float g_qk[NTOK * NHD * DIM];
__device__ float g_scores[BATCH * NBOX * NHD * NPATCH];
__device__ float g_u[NTOK * NHD * DIM];
__device__ float g_ctx[NTOK * DIM];
__device__ float g_comb[NTOK * DIM];
__device__ float g_ln[NTOK * DIM];
__device__ float g_hidden[NTOK * DFF];
__device__ float g_rows[NTOK * DIM];
__device__ float g_part[5505024];          // split-K partial scratch (22 MB)

// ------------------------- cp.async helpers ----------------------------------
__device__ __forceinline__ void cp16(void* smem, const void* gmem, bool pred) {
    unsigned sa = (unsigned)__cvta_generic_to_shared(smem);
    int sz = pred ? 16 : 0;
    asm volatile("cp.async.cg.shared.global [%0], [%1], 16, %2;\n"
                 :: "r"(sa), "l"(gmem), "r"(sz));
}
__device__ __forceinline__ void cp_commit() {
    asm volatile("cp.async.commit_group;\n");
}
template<int NWAIT>
__device__ __forceinline__ void cp_wait() {
    asm volatile("cp.async.wait_group %0;\n" :: "n"(NWAIT));
}

__device__ __forceinline__ void mbar_wait(unsigned mb, int phase) {
    asm volatile(
        "{\n\t.reg .pred P;\n\t"
        "WL_%=:\n\t"
        "mbarrier.try_wait.parity.acquire.cta.shared::cta.b64 P, [%0], %1, 0x989680;\n\t"
        "@P bra WD_%=;\n\t"
        "bra WL_%=;\n\t"
        "WD_%=:\n\t}"
        :: "r"(mb), "r"(phase) : "memory");
}

// ------------------------- simple kernels ------------------------------------
__global__ void copy_kernel(const float4* __restrict__ src, float4* __restrict__ dst, long n4) {
    long i = (long)blockIdx.x * blockDim.x + threadIdx.x;
    long stride = (long)gridDim.x * blockDim.x;
    for (; i < n4; i += stride) dst[i] = src[i];
}

__global__ void scan_kernel(const int* __restrict__ ids,
                            const unsigned char* __restrict__ mask,
                            const int* __restrict__ tokPtr) {
    int b = blockIdx.x;
    __shared__ int sh[SEQ];
    __shared__ int s_f0, s_es, s_off, s_first;
    int tid = threadIdx.x;

    if (tid == 0) s_f0 = 0x7fffffff;
    __syncthreads();
    for (int i = tid; i < SEQ; i += blockDim.x) {
        if (mask[i] != 0) { atomicMin(&s_f0, i); break; }
    }
    __syncthreads();
    if (tid == 0) {
        int f0 = s_f0;
        unsigned char b0 = mask[f0];
        unsigned char b1 = mask[f0 + 1];
        if (b0 == 1u && b1 == 0u)      { s_es = 4; s_off = 0; }
        else if (b0 == 0x80u)          { s_es = 4; s_off = 2; }
        else                           { s_es = 1; s_off = 0; }
        s_first = SEQ;
    }
    __syncthreads();
    int es = s_es, off = s_off;
    for (int i = tid; i < SEQ; i += blockDim.x)
        if (mask[((long)b * SEQ + i) * es + off] != 0) atomicMin(&s_first, i);
    __syncthreads();
    if (tid == 0) g_start[b] = s_first;

    for (int i = tid; i < SEQ; i += blockDim.x)
        sh[i] = ids[(long)b * SEQ + i];
    __syncthreads();
    if (tid < 32) {
        int tok = *tokPtr;
        int count = 0;
        for (int base = 0; base < SEQ && count < NBOX; base += 32) {
            unsigned bal = __ballot_sync(0xffffffffu, sh[base + tid] == tok);
            while (bal && count < NBOX) {
                int o = __ffs(bal) - 1;
                if (tid == 0) g_pos[b * NBOX + count] = base + o;
                count++;
                bal &= bal - 1;
            }
        }
    }
}

__global__ void gather_kernel(const float* __restrict__ emb) {
    int r = blockIdx.x;
    int b = r / NBOX;
    const float* src = emb + ((long)b * SEQ + g_pos[r]) * DIM;
    for (int i = threadIdx.x; i < DIM; i += blockDim.x) g_qtok[(long)r * DIM + i] = src[i];
}

__global__ void scatter_kernel(float* __restrict__ out) {
    int r = blockIdx.x;
    int b = r / NBOX;
    float* dst = out + ((long)b * SEQ + g_pos[r]) * DIM;
    for (int i = threadIdx.x; i < DIM; i += blockDim.x) dst[i] = g_rows[(long)r * DIM + i];
}

// ------------------------- skinny TMA tf32 mma GEMM (TB, 4-buffer ring) ------
// C[24,N] = A[24,K] @ W[N,K]^T via TMA SW128 tiles. BM=32 (rows 24..31 garbage,
// never stored), BN=64, BK=32, 128 threads. buf=t&3, phase=(t>>2)&1 — no
// indexed arrays, no modulo. Up to 3 tiles in flight during compute.
__global__ __launch_bounds__(TPBS) void skinny_tma(
    const __grid_constant__ CUtensorMap mapA,
    const __grid_constant__ CUtensorMap mapW,
    int zxA, int zyW,
    float* __restrict__ P, int N, int K, int SK)
{
    extern __shared__ __align__(1024) unsigned char sm[];
    __shared__ unsigned long long mbar[4];

    const int z = blockIdx.z, s = blockIdx.y;
    const int n0 = blockIdx.x * 64;
    const int Kc = K / SK;
    const int kBeg = s * Kc;
    const int nT = Kc / 32;

    const int tid  = threadIdx.x;
    const int wid  = tid >> 5;
    const int lane = tid & 31;
    const int grp  = lane >> 2;
    const int th   = lane & 3;

    unsigned smU = (unsigned)__cvta_generic_to_shared(sm);
    unsigned mbU = (unsigned)__cvta_generic_to_shared(mbar);

    if (tid == 0) {
#pragma unroll
        for (int i = 0; i < 4; i++)
            asm volatile("mbarrier.init.shared.b64 [%0], 1;" :: "r"(mbU + i * 8) : "memory");
    }
    __syncthreads();

    auto issue = [&](int t) {
        int buf = t & 3;
        unsigned mb = mbU + buf * 8;
        asm volatile("mbarrier.arrive.expect_tx.shared.b64 _, [%0], %1;"
                     :: "r"(mb), "r"(11264u) : "memory");
        int x = kBeg + t * 32;
        unsigned aA = smU + buf * TMA_STAGE;
        unsigned aB = aA + 4096;
        asm volatile(
            "cp.async.bulk.tensor.2d.shared::cta.global.tile.mbarrier::complete_tx::bytes "
            "[%0], [%1, {%2, %3}], [%4];"
            :: "r"(aA), "l"(&mapA), "r"(zxA * z + x), "r"(0), "r"(mb) : "memory");
        asm volatile(
            "cp.async.bulk.tensor.2d.shared::cta.global.tile.mbarrier::complete_tx::bytes "
            "[%0], [%1, {%2, %3}], [%4];"
            :: "r"(aB), "l"(&mapW), "r"(x), "r"(zyW * z + n0), "r"(mb) : "memory");
    };

    if (tid == 0) {
        issue(0);
        if (nT > 1) issue(1);
        if (nT > 2) issue(2);
        if (nT > 3) issue(3);
    }

    float c[2][2][4];
#pragma unroll
    for (int i = 0; i < 2; i++)
#pragma unroll
        for (int j = 0; j < 2; j++)
#pragma unroll
            for (int r = 0; r < 4; r++) c[i][j][r] = 0.f;

    const unsigned cx = (unsigned)(grp << 4);   // SW128 col-xor

    for (int t = 0; t < nT; t++) {
        const int buf = t & 3;
        mbar_wait(mbU + buf * 8, (t >> 2) & 1);

        const unsigned char* base = sm + buf * TMA_STAGE;
        const unsigned char* aT = base;
        const unsigned char* bT = base + 4096;

#pragma unroll
        for (int q = 0; q < 32; q += 8) {
            unsigned c0 = ((unsigned)((q + th) * 4)) ^ cx;
            unsigned c1 = ((unsigned)((q + th + 4) * 4)) ^ cx;
            unsigned a[2][4], b[2][2];
#pragma unroll
            for (int mt = 0; mt < 2; mt++) {
                int r = mt * 16 + grp;
                a[mt][0] = *(const unsigned*)(aT + r * 128 + c0);
                a[mt][1] = *(const unsigned*)(aT + (r + 8) * 128 + c0);
                a[mt][2] = *(const unsigned*)(aT + r * 128 + c1);
                a[mt][3] = *(const unsigned*)(aT + (r + 8) * 128 + c1);
            }
#pragma unroll
            for (int fn = 0; fn < 2; fn++) {
                int col = wid * 16 + fn * 8 + grp;
                b[fn][0] = *(const unsigned*)(bT + col * 128 + c0);
                b[fn][1] = *(const unsigned*)(bT + col * 128 + c1);
            }
#pragma unroll
            for (int mt = 0; mt < 2; mt++)
#pragma unroll
                for (int fn = 0; fn < 2; fn++) {
                    asm volatile(
                        "mma.sync.aligned.m16n8k8.row.col.f32.tf32.tf32.f32 "
                        "{%0,%1,%2,%3}, {%4,%5,%6,%7}, {%8,%9}, {%0,%1,%2,%3};"
                        : "+f"(c[mt][fn][0]), "+f"(c[mt][fn][1]),
                          "+f"(c[mt][fn][2]), "+f"(c[mt][fn][3])
                        : "r"(a[mt][0]), "r"(a[mt][1]), "r"(a[mt][2]), "r"(a[mt][3]),
                          "r"(b[fn][0]), "r"(b[fn][1]));
                }
        }
        __syncthreads();
        if (t + 4 < nT && tid == 0) issue(t + 4);
    }

    long base2 = (long)(z * SK + s) * NTOK * N;
#pragma unroll
    for (int mt = 0; mt < 2; mt++) {
        int r0 = mt * 16 + grp;
#pragma unroll
        for (int fn = 0; fn < 2; fn++) {
            int col = n0 + wid * 16 + fn * 8 + th * 2;
            *reinterpret_cast<float2*>(&P[base2 + (long)r0 * N + col]) =
                make_float2(c[mt][fn][0], c[mt][fn][1]);
            if (mt == 0)
                *reinterpret_cast<float2*>(&P[base2 + (long)(r0 + 8) * N + col]) =
                    make_float2(c[mt][fn][2], c[mt][fn][3]);
        }
    }
}

// ------------------------- skinny cp.async tf32 mma GEMM (NN) ----------------
// Output addressing generalized: addr = z*zOut + s*sOut + m*ldcOut + col.
template<bool TB>
__global__ __launch_bounds__(TPBS) void skinny_mma(
    const float* __restrict__ A, int lda, long Az,
    const float* __restrict__ W, int ldw, long Wz,
    float* __restrict__ P, int N, int K, int SK,
    long zOut, long sOut, int ldcOut)
{
    __shared__ float smem[2][SSTG];
    const int z = blockIdx.z, s = blockIdx.y;
    const int n0 = blockIdx.x * 64;
    const int Kc = K / SK;
    const int kBeg = s * Kc;
    A += (long)z * Az;
    W += (long)z * Wz;

    const int tid  = threadIdx.x;
    const int wid  = tid >> 5;
    const int lane = tid & 31;
    const int grp  = lane >> 2;
    const int th   = lane & 3;

    auto load_tile = [&](int t, int buf) {
        float* As = smem[buf];
        float* Bp = smem[buf] + 1152;
        const int k0 = kBeg + t * 32;
#pragma unroll
        for (int it = 0; it < 2; it++) {
            int idx = tid + it * TPBS;
            int m = idx >> 3, kc = idx & 7;
            cp16(&As[m * 36 + kc * 4], A + (long)m * lda + k0 + kc * 4, m < NTOK);
        }
        if (TB) {
#pragma unroll
            for (int it = 0; it < 4; it++) {
                int idx = tid + it * TPBS;
                int nn = idx >> 3, kc = idx & 7;
                cp16(&Bp[nn * 36 + kc * 4],
                     W + (long)(n0 + nn) * ldw + k0 + kc * 4, n0 + nn < N);
            }
        } else {
#pragma unroll
            for (int it = 0; it < 4; it++) {
                int idx = tid + it * TPBS;
                int kk = idx >> 4, nc = idx & 15;
                cp16(&Bp[kk * 72 + nc * 4],
                     W + (long)(k0 + kk) * ldw + n0 + nc * 4, n0 + nc * 4 < N);
            }
        }
        cp_commit();
    };

    float c[2][2][4];
#pragma unroll
    for (int i = 0; i < 2; i++)
#pragma unroll
        for (int j = 0; j < 2; j++)
#pragma unroll
            for (int r = 0; r < 4; r++) c[i][j][r] = 0.f;

    const int nT = Kc / 32;
    load_tile(0, 0);
    for (int t = 0; t < nT; t++) {
        const int buf = t & 1;
        if (t + 1 < nT) { load_tile(t + 1, buf ^ 1); cp_wait<1>(); }
        else            { cp_wait<0>(); }
        __syncthreads();

        const float* As = smem[buf];
        const float* Bp = smem[buf] + 1152;

#pragma unroll
        for (int q = 0; q < 32; q += 8) {
            unsigned a[2][4], b[2][2];
#pragma unroll
            for (int mt = 0; mt < 2; mt++) {
                int row = mt * 16 + grp;
                const unsigned* ap  = reinterpret_cast<const unsigned*>(&As[row * 36 + q + th]);
                const unsigned* ap8 = reinterpret_cast<const unsigned*>(&As[(row + 8) * 36 + q + th]);
                a[mt][0] = ap[0];
                a[mt][1] = ap8[0];
                a[mt][2] = ap[4];
                a[mt][3] = ap8[4];
            }
#pragma unroll
            for (int fn = 0; fn < 2; fn++) {
                int col = wid * 16 + fn * 8 + grp;
                if (TB) {
                    const unsigned* bp = reinterpret_cast<const unsigned*>(&Bp[col * 36 + q + th]);
                    b[fn][0] = bp[0];
                    b[fn][1] = bp[4];
                } else {
                    b[fn][0] = reinterpret_cast<const unsigned*>(&Bp[(q + th) * 72 + col])[0];
                    b[fn][1] = reinterpret_cast<const unsigned*>(&Bp[(q + th + 4) * 72 + col])[0];
                }
            }
#pragma unroll
            for (int mt = 0; mt < 2; mt++)
#pragma unroll
                for (int fn = 0; fn < 2; fn++) {
                    asm volatile(
                        "mma.sync.aligned.m16n8k8.row.col.f32.tf32.tf32.f32 "
                        "{%0,%1,%2,%3}, {%4,%5,%6,%7}, {%8,%9}, {%0,%1,%2,%3};"
                        : "+f"(c[mt][fn][0]), "+f"(c[mt][fn][1]),
                          "+f"(c[mt][fn][2]), "+f"(c[mt][fn][3])
                        : "r"(a[mt][0]), "r"(a[mt][1]), "r"(a[mt][2]), "r"(a[mt][3]),
                          "r"(b[fn][0]), "r"(b[fn][1]));
                }
        }
        __syncthreads();
    }

    long base = (long)z * zOut + (long)s * sOut;
#pragma unroll
    for (int mt = 0; mt < 2; mt++) {
        int r0 = mt * 16 + grp;
#pragma unroll
        for (int fn = 0; fn < 2; fn++) {
            int col = n0 + wid * 16 + fn * 8 + th * 2;
            if (col < N) {
                *reinterpret_cast<float2*>(&P[base + (long)r0 * ldcOut + col]) =
                    make_float2(c[mt][fn][0], c[mt][fn][1]);
                if (mt == 0)
                    *reinterpret_cast<float2*>(&P[base + (long)(r0 + 8) * ldcOut + col]) =
                        make_float2(c[mt][fn][2], c[mt][fn][3]);
            }
        }
    }
}

// ------------------------- big tf32 mma GEMM (M=96, 3-stage pipeline) --------
template<bool TB>
__global__ __launch_bounds__(TPB) void mma_gemm(
    const float* __restrict__ A, long Az,
    const float* __restrict__ B, long Bz,
    float* __restrict__ P, int N, int K, int SK,
    const int* __restrict__ patchStart)
{
    extern __shared__ float smem[];
    const int z = blockIdx.z, s = blockIdx.y;
    const int n0 = blockIdx.x * 64;
    const int kLen = K / SK;
    const int kBeg = s * kLen;
    A += (long)z * Az;
    B += (long)z * Bz + (long)patchStart[z] * DIM;

    const int tid  = threadIdx.x;
    const int wid  = tid >> 5;
    const int lane = tid & 31;
    const int grp  = lane >> 2;
    const int th   = lane & 3;
    const int warpM = wid >> 2;
    const int warpN = wid & 3;

    auto load_tile = [&](int t, int buf) {
        float* As = smem + buf * STG;
        float* Bp = smem + buf * STG + 3456;
        const int k0 = kBeg + t * 32;
#pragma unroll
        for (int it = 0; it < 3; it++) {
            int idx = tid + it * TPB;
            int m = idx >> 3, kc = idx & 7;
            cp16(&As[m * 36 + kc * 4], A + (long)m * K + k0 + kc * 4, true);
        }
        if (TB) {
#pragma unroll
            for (int it = 0; it < 2; it++) {
                int idx = tid + it * TPB;
                int nn = idx >> 3, kc = idx & 7;
                cp16(&Bp[nn * 36 + kc * 4], B + (long)(n0 + nn) * DIM + k0 + kc * 4, true);
            }
        } else {
#pragma unroll
            for (int it = 0; it < 2; it++) {
                int idx = tid + it * TPB;
                int kk = idx >> 4, nc = idx & 15;
                cp16(&Bp[kk * 72 + nc * 4], B + (long)(k0 + kk) * DIM + n0 + nc * 4, true);
            }
        }
        cp_commit();
    };

    float c[3][2][4];
#pragma unroll
    for (int i = 0; i < 3; i++)
#pragma unroll
        for (int j = 0; j < 2; j++)
#pragma unroll
            for (int r = 0; r < 4; r++) c[i][j][r] = 0.f;

    const int nT = kLen / 32;
    load_tile(0, 0);
    if (nT > 1) load_tile(1, 1);
    for (int t = 0; t < nT; t++) {
        const int buf = t % 3;
        if (t + 2 < nT) load_tile(t + 2, (t + 2) % 3);
        int ahead = nT - 1 - t;
        if (ahead >= 2)      cp_wait<2>();
        else if (ahead == 1) cp_wait<1>();
        else                 cp_wait<0>();
        __syncthreads();

        const float* As = smem + buf * STG;
        const float* Bp = smem + buf * STG + 3456;

#pragma unroll
        for (int q = 0; q < 32; q += 8) {
            unsigned a[3][4], b[2][2];
#pragma unroll
            for (int fr = 0; fr < 3; fr++) {
                int row = warpM * 48 + fr * 16 + grp;
                const unsigned* ap  = reinterpret_cast<const unsigned*>(&As[row * 36 + q + th]);
                const unsigned* ap8 = reinterpret_cast<const unsigned*>(&As[(row + 8) * 36 + q + th]);
                a[fr][0] = ap[0];
                a[fr][1] = ap8[0];
                a[fr][2] = ap[4];
                a[fr][3] = ap8[4];
            }
#pragma unroll
            for (int fn = 0; fn < 2; fn++) {
                int col = warpN * 16 + fn * 8 + grp;
                if (TB) {
                    const unsigned* bp = reinterpret_cast<const unsigned*>(&Bp[col * 36 + q + th]);
                    b[fn][0] = bp[0];
                    b[fn][1] = bp[4];
                } else {
                    b[fn][0] = reinterpret_cast<const unsigned*>(&Bp[(q + th) * 72 + col])[0];
                    b[fn][1] = reinterpret_cast<const unsigned*>(&Bp[(q + th + 4) * 72 + col])[0];
                }
            }
#pragma unroll
            for (int fr = 0; fr < 3; fr++)
#pragma unroll
                for (int fn = 0; fn < 2; fn++) {
                    asm volatile(
                        "mma.sync.aligned.m16n8k8.row.col.f32.tf32.tf32.f32 "
                        "{%0,%1,%2,%3}, {%4,%5,%6,%7}, {%8,%9}, {%0,%1,%2,%3};"
                        : "+f"(c[fr][fn][0]), "+f"(c[fr][fn][1]),
                          "+f"(c[fr][fn][2]), "+f"(c[fr][fn][3])
                        : "r"(a[fr][0]), "r"(a[fr][1]), "r"(a[fr][2]), "r"(a[fr][3]),
                          "r"(b[fn][0]), "r"(b[fn][1]));
                }
        }
        __syncthreads();
    }

    long base = (long)(z * SK + s) * 96 * N;
#pragma unroll
    for (int fr = 0; fr < 3; fr++) {
        int r0 = warpM * 48 + fr * 16 + grp;
#pragma unroll
        for (int fn = 0; fn < 2; fn++) {
            int col = n0 + warpN * 16 + fn * 8 + th * 2;
            *reinterpret_cast<float2*>(&P[base + (long)r0 * N + col]) =
                make_float2(c[fr][fn][0], c[fr][fn][1]);
            *reinterpret_cast<float2*>(&P[base + (long)(r0 + 8) * N + col]) =
                make_float2(c[fr][fn][2], c[fr][fn][3]);
        }
    }
}

// reduce split-K partials + epilogue
__global__ void combine_kernel(const float* __restrict__ P, int SK,
                               float* __restrict__ C, int ldc, long Cz, int M, int N,
                               const float* __restrict__ bias, long biasZ,
                               const float* __restrict__ resid, long residZ,
                               float scale, int act, int total) {
    int idx = blockIdx.x * blockDim.x + threadIdx.x;
    if (idx >= total) return;
    int n = idx % N;
    int t = idx / N;
    int m = t % M;
    int z = t / M;
    float v = 0.f;
    for (int s = 0; s < SK; s++) v += P[((long)(z * SK + s) * M + m) * N + n];
    if (bias)  v += bias[z * biasZ + n];
    v *= scale;
    if (act)   v = v * normcdff(v);
    if (resid) v += resid[z * residZ + (long)m * ldc + n];
    C[z * Cz + (long)m * ldc + n] = v;
}

// ------------------------- masked softmax (fuses score split-K reduce) -------
__global__ void softmax_kernel(const float* __restrict__ P,
                               float* __restrict__ attn,
                               const float* __restrict__ boxes,
                               const int* __restrict__ thw) {
    int blk = blockIdx.x;
    int b = blk / (NBOX * NHD);
    int n = (blk / NHD) % NBOX;
    int h = blk % NHD;
    int m = n * NHD + h;
    int hg = thw[1], wg = thw[2];
    const float* bx = boxes + (long)(b * NBOX + n) * 4;
    float x1 = bx[0], y1 = bx[1], x2 = bx[2], y2 = bx[3];
    int px1 = min(max((int)floorf(x1 * (float)wg), 0), wg - 1);
    int px2 = max(px1 + 1, min((int)floorf(x2 * (float)wg), wg));
    int py1 = min(max((int)floorf(y1 * (float)hg), 0), hg - 1);
    int py2 = max(py1 + 1, min((int)floorf(y2 * (float)hg), hg));

    const float* r0 = P + ((long)(b * 4 + 0) * 96 + m) * NPATCH;
    const float* r1 = P + ((long)(b * 4 + 1) * 96 + m) * NPATCH;
    const float* r2 = P + ((long)(b * 4 + 2) * 96 + m) * NPATCH;
    const float* r3 = P + ((long)(b * 4 + 3) * 96 + m) * NPATCH;
    float* orow = attn + (long)blk * NPATCH;

    __shared__ float sh[NPATCH];
    __shared__ float red[TPB];
    int tid = threadIdx.x;
    int hw = hg * wg;

    float mx = -1e30f;
    for (int i = tid; i < NPATCH; i += TPB) {
        int q = i % hw;
        int rr = q / wg, cc = q % wg;
        bool in = (rr >= py1) && (rr < py2) && (cc >= px1) && (cc < px2);
        float v = in ? (r0[i] + r1[i] + r2[i] + r3[i]) : -1e30f;
        sh[i] = v;
        mx = fmaxf(mx, v);
    }
    red[tid] = mx;
    __syncthreads();
    for (int s = TPB / 2; s > 0; s >>= 1) {
        if (tid < s) red[tid] = fmaxf(red[tid], red[tid + s]);
        __syncthreads();
    }
    float maxv = red[0];
    __syncthreads();

    float sum = 0.f;
    for (int i = tid; i < NPATCH; i += TPB) {
        float e = expf(sh[i] - maxv);
        sh[i] = e;
        sum += e;
    }
    red[tid] = sum;
    __syncthreads();
    for (int s = TPB / 2; s > 0; s >>= 1) {
        if (tid < s) red[tid] += red[tid + s];
        __syncthreads();
    }
    float inv = 1.f / red[0];
    __syncthreads();
    for (int i = tid; i < NPATCH; i += TPB) orow[i] = sh[i] * inv;
}

// ------------------------- layernorm (fuses combined split-K reduce) ---------
__global__ void ln_fused_kernel(const float* __restrict__ P,
                                const float* __restrict__ bout,
                                const float* __restrict__ gamma,
                                const float* __restrict__ beta) {
    int r = blockIdx.x;
    __shared__ float red[TPB];
    __shared__ float red2[TPB];
    int tid = threadIdx.x;
    float s = 0.f, s2 = 0.f;
    for (int i = tid; i < DIM; i += TPB) {
        float v = bout[i] + g_qtok[(long)r * DIM + i];
#pragma unroll
        for (int k = 0; k < 16; k++)
            v += P[((long)(k * NTOK) + r) * DIM + i];
        g_comb[(long)r * DIM + i] = v;
        s += v;
        s2 += v * v;
    }
    red[tid] = s; red2[tid] = s2;
    __syncthreads();
    for (int st = TPB / 2; st > 0; st >>= 1) {
        if (tid < st) { red[tid] += red[tid + st]; red2[tid] += red2[tid + st]; }
        __syncthreads();
    }
    float mu = red[0] / DIM;
    float var = red2[0] / DIM - mu * mu;
    float inv = rsqrtf(var + 1e-5f);
    for (int i = tid; i < DIM; i += TPB)
        g_ln[(long)r * DIM + i] = (g_comb[(long)r * DIM + i] - mu) * inv * gamma[i] + beta[i];
}

// ------------------------- host tensormap helper -----------------------------
typedef CUresult (*EncodeFn)(
    CUtensorMap*, CUtensorMapDataType, cuuint32_t, void*,
    const cuuint64_t*, const cuuint64_t*, const cuuint32_t*, const cuuint32_t*,
    CUtensorMapInterleave, CUtensorMapSwizzle, CUtensorMapL2promotion,
    CUtensorMapFloatOOBfill);

static void encode_map(EncodeFn fn, CUtensorMap* m, void* ptr,
                       unsigned long long width, unsigned long long height,
                       unsigned long long strideBytes,
                       unsigned boxW, unsigned boxH) {
    cuuint64_t dims[2]    = { width, height };
    cuuint64_t strides[1] = { strideBytes };
    cuuint32_t box[2]     = { boxW, boxH };
    cuuint32_t es[2]      = { 1, 1 };
    fn(m, CU_TENSOR_MAP_DATA_TYPE_FLOAT32, 2, ptr, dims, strides, box, es,
       CU_TENSOR_MAP_INTERLEAVE_NONE, CU_TENSOR_MAP_SWIZZLE_128B,
       CU_TENSOR_MAP_L2_PROMOTION_L2_128B, CU_TENSOR_MAP_FLOAT_OOB_FILL_NONE);
}

// ------------------------- launch --------------------------------------------
extern "C" void kernel_launch(void* const* d_in, const int* in_sizes, int n_in,
                              void* d_out, int out_size) {
    const float*         emb   = (const float*)d_in[0];
    const int*           ids   = (const int*)d_in[1];
    const unsigned char* msk   = (const unsigned char*)d_in[2];
    const float*         boxes = (const float*)d_in[3];
    const int*           thw   = (const int*)d_in[4];
    const int*           tok   = (const int*)d_in[5];
    const float*         Win   = (const float*)d_in[6];
    const float*         bin   = (const float*)d_in[7];
    const float*         Wout  = (const float*)d_in[8];
    const float*         bout  = (const float*)d_in[9];
    const float*         gam   = (const float*)d_in[10];
    const float*         bet   = (const float*)d_in[11];
    const float*         W1    = (const float*)d_in[12];
    const float*         b1    = (const float*)d_in[13];
    const float*         W2    = (const float*)d_in[14];
    const float*         b2    = (const float*)d_in[15];
    float*               out   = (float*)d_out;

    const float* Wq = Win;
    const float* Wk = Win + (long)DIM * DIM;
    const float* Wv = Win + 2L * DIM * DIM;
    const float* bv = bin + 2L * DIM;

    float *qtok, *q, *qk, *scores, *u, *ctx, *ln, *hidden, *rows, *part;
    int *start;
    cudaGetSymbolAddress((void**)&qtok,   g_qtok);
    cudaGetSymbolAddress((void**)&q,      g_q);
    cudaGetSymbolAddress((void**)&qk,     g_qk);
    cudaGetSymbolAddress((void**)&scores, g_scores);
    cudaGetSymbolAddress((void**)&u,      g_u);
    cudaGetSymbolAddress((void**)&ctx,    g_ctx);
    cudaGetSymbolAddress((void**)&ln,     g_ln);
    cudaGetSymbolAddress((void**)&hidden, g_hidden);
    cudaGetSymbolAddress((void**)&rows,   g_rows);
    cudaGetSymbolAddress((void**)&part,   g_part);
    cudaGetSymbolAddress((void**)&start,  g_start);

    cudaFuncSetAttribute(mma_gemm<true>,  cudaFuncAttributeMaxDynamicSharedMemorySize, SMEM_BYTES);
    cudaFuncSetAttribute(mma_gemm<false>, cudaFuncAttributeMaxDynamicSharedMemorySize, SMEM_BYTES);
    cudaFuncSetAttribute(skinny_tma,      cudaFuncAttributeMaxDynamicSharedMemorySize, TMA_SMEM);

    // tensormaps for TMA weight streaming
    EncodeFn enc = nullptr;
    cudaGetDriverEntryPoint("cuTensorMapEncodeTiled", (void**)&enc, cudaEnableDefault);
    CUtensorMap mQtok, mU, mCtx, mLn, mHid, mWq, mWv, mWout, mW1, mW2;
    encode_map(enc, &mQtok, qtok,        DIM, NTOK, (unsigned long long)DIM * 4,       32, 24);
    encode_map(enc, &mU,    u,           (unsigned long long)NHD * DIM, NTOK,
                                                    (unsigned long long)NHD * DIM * 4, 32, 24);
    encode_map(enc, &mCtx,  ctx,         DIM, NTOK, (unsigned long long)DIM * 4,       32, 24);
    encode_map(enc, &mLn,   ln,          DIM, NTOK, (unsigned long long)DIM * 4,       32, 24);
    encode_map(enc, &mHid,  hidden,      DFF, NTOK, (unsigned long long)DFF * 4,       32, 24);
    encode_map(enc, &mWq,   (void*)Wq,   DIM, DIM,  (unsigned long long)DIM * 4,       32, 64);
    encode_map(enc, &mWv,   (void*)Wv,   DIM, DIM,  (unsigned long long)DIM * 4,       32, 64);
    encode_map(enc, &mWout, (void*)Wout, DIM, DIM,  (unsigned long long)DIM * 4,       32, 64);
    encode_map(enc, &mW1,   (void*)W1,   DIM, DFF,  (unsigned long long)DIM * 4,       32, 64);
    encode_map(enc, &mW2,   (void*)W2,   DFF, DIM,  (unsigned long long)DFF * 4,       32, 64);

    const float scale = 1.0f / sqrtf((float)DHD);
    const long n4 = (long)BATCH * SEQ * DIM / 4;

    // ---- fork: base copy on side stream ----
    cudaStream_t s2;
    cudaStreamCreate(&s2);
    cudaEvent_t eFork, eJoin;
    cudaEventCreateWithFlags(&eFork, cudaEventDisableTiming);
    cudaEventCreateWithFlags(&eJoin, cudaEventDisableTiming);
    cudaEventRecord(eFork, 0);
    cudaStreamWaitEvent(s2, eFork, 0);
    copy_kernel<<<8192, TPB, 0, s2>>>((const float4*)emb, (float4*)out, n4);
    cudaEventRecord(eJoin, s2);

    // ---- main chain ----
    scan_kernel<<<BATCH, TPB>>>(ids, msk, tok);
    gather_kernel<<<NTOK, TPB>>>(emb);

    // 4. q = (qtok @ Wq^T + bq) * scale   (TMA, SK=16, Kc=224)
    skinny_tma<<<dim3(56, 16, 1), TPBS, TMA_SMEM>>>(mQtok, mWq, 0, 0, part, DIM, DIM, 16);
    combine_kernel<<<(NTOK * DIM + TPB - 1) / TPB, TPB>>>(
        part, 16, q, DIM, 0, NTOK, DIM, bin, 0, nullptr, 0, scale, 0, NTOK * DIM);

    // 5. qk[t,h,:] = q[t,h,:] @ Wk_h   (cp.async NN per head, SK=1, DIRECT write)
    skinny_mma<false><<<dim3(56, 1, NHD), TPBS>>>(q, DIM, DHD, Wk, DIM, (long)DHD * DIM,
                                                  qk, DIM, DHD, 1,
                                                  (long)DIM, 0, NHD * DIM);

    // 6. scores = qk @ patches^T   (SK=4) -> partials consumed by softmax
    mma_gemm<true><<<dim3(NPATCH / 64, 4, BATCH), TPB, SMEM_BYTES>>>(
        qk, (long)96 * DIM, emb, (long)SEQ * DIM,
        part, NPATCH, DIM, 4, start);

    // 7. masked softmax
    softmax_kernel<<<BATCH * NBOX * NHD, TPB>>>(part, scores, boxes, thw);

    // 8. u = attn @ patches   (SK=4)
    mma_gemm<false><<<dim3(DIM / 64, 4, BATCH), TPB, SMEM_BYTES>>>(
        scores, (long)96 * NPATCH, emb, (long)SEQ * DIM,
        part, DIM, NPATCH, 4, start);
    combine_kernel<<<(BATCH * 96 * DIM + TPB - 1) / TPB, TPB>>>(
        part, 4, u, DIM, (long)96 * DIM, 96, DIM,
        nullptr, 0, nullptr, 0, 1.f, 0, BATCH * 96 * DIM);

    // 9. ctx[:, h] = u_h @ Wv_h^T + bv_h   (TMA per head)
    skinny_tma<<<dim3(7, 16, NHD), TPBS, TMA_SMEM>>>(mU, mWv, DIM, DHD, part, DHD, DIM, 16);
    combine_kernel<<<(NHD * NTOK * DHD + TPB - 1) / TPB, TPB>>>(
        part, 16, ctx, DIM, DHD, NTOK, DHD, bv, DHD, nullptr, 0, 1.f, 0,
        NHD * NTOK * DHD);

    // 10. combined partials = ctx @ Wout^T   (TMA, SK=16) -> ln_fused
    skinny_tma<<<dim3(56, 16, 1), TPBS, TMA_SMEM>>>(mCtx, mWout, 0, 0, part, DIM, DIM, 16);

    // 11. layernorm (reduces 16 partials + bout + qtok residual)
    ln_fused_kernel<<<NTOK, TPB>>>(part, bout, gam, bet);

    // 12. hidden = gelu(ln @ W1^T + b1)   (TMA, SK=8, Kc=448)
    skinny_tma<<<dim3(112, 8, 1), TPBS, TMA_SMEM>>>(mLn, mW1, 0, 0, part, DFF, DIM, 8);
    combine_kernel<<<(NTOK * DFF + TPB - 1) / TPB, TPB>>>(
        part, 8, hidden, DFF, 0, NTOK, DFF, b1, 0, nullptr, 0, 1.f, 1, NTOK * DFF);

    // 13. rows = ln + hidden @ W2^T + b2   (TMA, SK=16, Kc=448)
    skinny_tma<<<dim3(56, 16, 1), TPBS, TMA_SMEM>>>(mHid, mW2, 0, 0, part, DIM, DFF, 16);
    combine_kernel<<<(NTOK * DIM + TPB - 1) / TPB, TPB>>>(
        part, 16, rows, DIM, 0, NTOK, DIM, b2, 0, ln, 0, 1.f, 0, NTOK * DIM);

    // ---- join: copy must complete before scatter ----
    cudaStreamWaitEvent(0, eJoin, 0);
    scatter_kernel<<<NTOK, TPB>>>(out);
}

// round 13
// speedup vs baseline: 1.0281x; 1.0281x over previous
#include <cuda_runtime.h>
#include <cuda.h>
#include <math.h>

#define BATCH   2
#define SEQ     4608
#define DIM     3584
#define NHD     8
#define DHD     448
#define NPATCH  4096
#define NBOX    12
#define DFF     7168
#define NTOK    24
#define TPB     256
#define TPBS    128

#define STG     5760        // floats per stage (big mma)
#define SMEM_BYTES (3 * STG * 4)
#define SSTG    3456        // floats per stage (skinny cp.async mma)

// ------------------------- scratch ------------------------------------------
__device__ int   g_pos[NTOK];
__device__ int   g_start[BATCH];
__device__ float g_qtok[NTOK * DIM];
__device__ float g_q[NTOK * DIM];
__device__ float g_qk[NTOK * NHD * DIM];
__device__ float g_scores[BATCH * NBOX * NHD * NPATCH];
__device__ float g_u[NTOK * NHD * DIM];
__device__ float g_ctx[NTOK * DIM];
__device__ float g_comb[NTOK * DIM];
__device__ float g_ln[NTOK * DIM];
__device__ float g_hidden[NTOK * DFF];
__device__ float g_rows[NTOK * DIM];
__device__ float g_part[5505024];          // split-K partial scratch (22 MB)

// ------------------------- cp.async helpers ----------------------------------
__device__ __forceinline__ void cp16(void* smem, const void* gmem, bool pred) {
    unsigned sa = (unsigned)__cvta_generic_to_shared(smem);
    int sz = pred ? 16 : 0;
    asm volatile("cp.async.cg.shared.global [%0], [%1], 16, %2;\n"
                 :: "r"(sa), "l"(gmem), "r"(sz));
}
__device__ __forceinline__ void cp_commit() {
    asm volatile("cp.async.commit_group;\n");
}
template<int NWAIT>
__device__ __forceinline__ void cp_wait() {
    asm volatile("cp.async.wait_group %0;\n" :: "n"(NWAIT));
}

__device__ __forceinline__ void mbar_wait(unsigned mb, int phase) {
    asm volatile(
        "{\n\t.reg .pred P;\n\t"
        "WL_%=:\n\t"
        "mbarrier.try_wait.parity.acquire.cta.shared::cta.b64 P, [%0], %1, 0x989680;\n\t"
        "@P bra WD_%=;\n\t"
        "bra WL_%=;\n\t"
        "WD_%=:\n\t}"
        :: "r"(mb), "r"(phase) : "memory");
}

// ------------------------- simple kernels ------------------------------------
__global__ void scan_kernel(const int* __restrict__ ids,
                            const unsigned char* __restrict__ mask,
                            const int* __restrict__ tokPtr) {
    int b = blockIdx.x;
    __shared__ int sh[SEQ];
    __shared__ int s_f0, s_es, s_off, s_first;
    int tid = threadIdx.x;

    if (tid == 0) s_f0 = 0x7fffffff;
    __syncthreads();
    for (int i = tid; i < SEQ; i += blockDim.x) {
        if (mask[i] != 0) { atomicMin(&s_f0, i); break; }
    }
    __syncthreads();
    if (tid == 0) {
        int f0 = s_f0;
        unsigned char b0 = mask[f0];
        unsigned char b1 = mask[f0 + 1];
        if (b0 == 1u && b1 == 0u)      { s_es = 4; s_off = 0; }
        else if (b0 == 0x80u)          { s_es = 4; s_off = 2; }
        else                           { s_es = 1; s_off = 0; }
        s_first = SEQ;
    }
    __syncthreads();
    int es = s_es, off = s_off;
    for (int i = tid; i < SEQ; i += blockDim.x)
        if (mask[((long)b * SEQ + i) * es + off] != 0) atomicMin(&s_first, i);
    __syncthreads();
    if (tid == 0) g_start[b] = s_first;

    for (int i = tid; i < SEQ; i += blockDim.x)
        sh[i] = ids[(long)b * SEQ + i];
    __syncthreads();
    if (tid < 32) {
        int tok = *tokPtr;
        int count = 0;
        for (int base = 0; base < SEQ && count < NBOX; base += 32) {
            unsigned bal = __ballot_sync(0xffffffffu, sh[base + tid] == tok);
            while (bal && count < NBOX) {
                int o = __ffs(bal) - 1;
                if (tid == 0) g_pos[b * NBOX + count] = base + o;
                count++;
                bal &= bal - 1;
            }
        }
    }
}

__global__ void gather_kernel(const float* __restrict__ emb) {
    int r = blockIdx.x;
    int b = r / NBOX;
    const float* src = emb + ((long)b * SEQ + g_pos[r]) * DIM;
    for (int i = threadIdx.x; i < DIM; i += blockDim.x) g_qtok[(long)r * DIM + i] = src[i];
}

__global__ void scatter_kernel(float* __restrict__ out) {
    int r = blockIdx.x;
    int b = r / NBOX;
    float* dst = out + ((long)b * SEQ + g_pos[r]) * DIM;
    for (int i = threadIdx.x; i < DIM; i += blockDim.x) dst[i] = g_rows[(long)r * DIM + i];
}

// ------------------------- skinny TMA tf32 mma GEMM (TB, 2-stage) ------------
// Round-10 configuration (13.7 us measured): static smem, 2 buffers.
// C[24,N] = A[24,K] @ W[N,K]^T via TMA SW128 tiles. BM=32 (rows 24..31
// garbage, never stored), BN=64, BK=32, 128 threads.
__global__ __launch_bounds__(TPBS) void skinny_tma(
    const __grid_constant__ CUtensorMap mapA,
    const __grid_constant__ CUtensorMap mapW,
    int zxA, int zyW,
    float* __restrict__ P, int N, int K, int SK)
{
    __shared__ __align__(1024) unsigned char sm[2 * 12288];
    __shared__ unsigned long long mbar[2];

    const int z = blockIdx.z, s = blockIdx.y;
    const int n0 = blockIdx.x * 64;
    const int Kc = K / SK;
    const int kBeg = s * Kc;
    const int nT = Kc / 32;

    const int tid  = threadIdx.x;
    const int wid  = tid >> 5;
    const int lane = tid & 31;
    const int grp  = lane >> 2;
    const int th   = lane & 3;

    unsigned smU = (unsigned)__cvta_generic_to_shared(sm);
    unsigned mbU = (unsigned)__cvta_generic_to_shared(mbar);

    if (tid == 0) {
        asm volatile("mbarrier.init.shared.b64 [%0], 1;" :: "r"(mbU) : "memory");
        asm volatile("mbarrier.init.shared.b64 [%0], 1;" :: "r"(mbU + 8) : "memory");
    }
    __syncthreads();

    auto issue = [&](int t, int buf) {
        unsigned mb = mbU + buf * 8;
        asm volatile("mbarrier.arrive.expect_tx.shared.b64 _, [%0], %1;"
                     :: "r"(mb), "r"(11264u) : "memory");
        int x = kBeg + t * 32;
        unsigned aA = smU + buf * 12288;
        unsigned aB = aA + 4096;
        asm volatile(
            "cp.async.bulk.tensor.2d.shared::cta.global.tile.mbarrier::complete_tx::bytes "
            "[%0], [%1, {%2, %3}], [%4];"
            :: "r"(aA), "l"(&mapA), "r"(zxA * z + x), "r"(0), "r"(mb) : "memory");
        asm volatile(
            "cp.async.bulk.tensor.2d.shared::cta.global.tile.mbarrier::complete_tx::bytes "
            "[%0], [%1, {%2, %3}], [%4];"
            :: "r"(aB), "l"(&mapW), "r"(x), "r"(zyW * z + n0), "r"(mb) : "memory");
    };

    if (tid == 0) { issue(0, 0); issue(1, 1); }

    float c[2][2][4];
#pragma unroll
    for (int i = 0; i < 2; i++)
#pragma unroll
        for (int j = 0; j < 2; j++)
#pragma unroll
            for (int r = 0; r < 4; r++) c[i][j][r] = 0.f;

    int ph0 = 0, ph1 = 0;
    const unsigned cx = (unsigned)(grp << 4);   // SW128 col-xor

    for (int t = 0; t < nT; t++) {
        const int buf = t & 1;
        if (buf == 0) { mbar_wait(mbU, ph0); ph0 ^= 1; }
        else          { mbar_wait(mbU + 8, ph1); ph1 ^= 1; }

        const unsigned char* base = sm + buf * 12288;
        const unsigned char* aT = base;
        const unsigned char* bT = base + 4096;

#pragma unroll
        for (int q = 0; q < 32; q += 8) {
            unsigned c0 = ((unsigned)((q + th) * 4)) ^ cx;
            unsigned c1 = ((unsigned)((q + th + 4) * 4)) ^ cx;
            unsigned a[2][4], b[2][2];
#pragma unroll
            for (int mt = 0; mt < 2; mt++) {
                int r = mt * 16 + grp;
                a[mt][0] = *(const unsigned*)(aT + r * 128 + c0);
                a[mt][1] = *(const unsigned*)(aT + (r + 8) * 128 + c0);
                a[mt][2] = *(const unsigned*)(aT + r * 128 + c1);
                a[mt][3] = *(const unsigned*)(aT + (r + 8) * 128 + c1);
            }
#pragma unroll
            for (int fn = 0; fn < 2; fn++) {
                int col = wid * 16 + fn * 8 + grp;
                b[fn][0] = *(const unsigned*)(bT + col * 128 + c0);
                b[fn][1] = *(const unsigned*)(bT + col * 128 + c1);
            }
#pragma unroll
            for (int mt = 0; mt < 2; mt++)
#pragma unroll
                for (int fn = 0; fn < 2; fn++) {
                    asm volatile(
                        "mma.sync.aligned.m16n8k8.row.col.f32.tf32.tf32.f32 "
                        "{%0,%1,%2,%3}, {%4,%5,%6,%7}, {%8,%9}, {%0,%1,%2,%3};"
                        : "+f"(c[mt][fn][0]), "+f"(c[mt][fn][1]),
                          "+f"(c[mt][fn][2]), "+f"(c[mt][fn][3])
                        : "r"(a[mt][0]), "r"(a[mt][1]), "r"(a[mt][2]), "r"(a[mt][3]),
                          "r"(b[fn][0]), "r"(b[fn][1]));
                }
        }
        __syncthreads();
        if (t + 2 < nT && tid == 0) issue(t + 2, buf);
    }

    long base2 = (long)(z * SK + s) * NTOK * N;
#pragma unroll
    for (int mt = 0; mt < 2; mt++) {
        int r0 = mt * 16 + grp;
#pragma unroll
        for (int fn = 0; fn < 2; fn++) {
            int col = n0 + wid * 16 + fn * 8 + th * 2;
            *reinterpret_cast<float2*>(&P[base2 + (long)r0 * N + col]) =
                make_float2(c[mt][fn][0], c[mt][fn][1]);
            if (mt == 0)
                *reinterpret_cast<float2*>(&P[base2 + (long)(r0 + 8) * N + col]) =
                    make_float2(c[mt][fn][2], c[mt][fn][3]);
        }
    }
}

// ------------------------- skinny cp.async tf32 mma GEMM (NN) ----------------
// Output addressing generalized: addr = z*zOut + s*sOut + m*ldcOut + col.
template<bool TB>
__global__ __launch_bounds__(TPBS) void skinny_mma(
    const float* __restrict__ A, int lda, long Az,
    const float* __restrict__ W, int ldw, long Wz,
    float* __restrict__ P, int N, int K, int SK,
    long zOut, long sOut, int ldcOut)
{
    __shared__ float smem[2][SSTG];
    const int z = blockIdx.z, s = blockIdx.y;
    const int n0 = blockIdx.x * 64;
    const int Kc = K / SK;
    const int kBeg = s * Kc;
    A += (long)z * Az;
    W += (long)z * Wz;

    const int tid  = threadIdx.x;
    const int wid  = tid >> 5;
    const int lane = tid & 31;
    const int grp  = lane >> 2;
    const int th   = lane & 3;

    auto load_tile = [&](int t, int buf) {
        float* As = smem[buf];
        float* Bp = smem[buf] + 1152;
        const int k0 = kBeg + t * 32;
#pragma unroll
        for (int it = 0; it < 2; it++) {
            int idx = tid + it * TPBS;
            int m = idx >> 3, kc = idx & 7;
            cp16(&As[m * 36 + kc * 4], A + (long)m * lda + k0 + kc * 4, m < NTOK);
        }
        if (TB) {
#pragma unroll
            for (int it = 0; it < 4; it++) {
                int idx = tid + it * TPBS;
                int nn = idx >> 3, kc = idx & 7;
                cp16(&Bp[nn * 36 + kc * 4],
                     W + (long)(n0 + nn) * ldw + k0 + kc * 4, n0 + nn < N);
            }
        } else {
#pragma unroll
            for (int it = 0; it < 4; it++) {
                int idx = tid + it * TPBS;
                int kk = idx >> 4, nc = idx & 15;
                cp16(&Bp[kk * 72 + nc * 4],
                     W + (long)(k0 + kk) * ldw + n0 + nc * 4, n0 + nc * 4 < N);
            }
        }
        cp_commit();
    };

    float c[2][2][4];
#pragma unroll
    for (int i = 0; i < 2; i++)
#pragma unroll
        for (int j = 0; j < 2; j++)
#pragma unroll
            for (int r = 0; r < 4; r++) c[i][j][r] = 0.f;

    const int nT = Kc / 32;
    load_tile(0, 0);
    for (int t = 0; t < nT; t++) {
        const int buf = t & 1;
        if (t + 1 < nT) { load_tile(t + 1, buf ^ 1); cp_wait<1>(); }
        else            { cp_wait<0>(); }
        __syncthreads();

        const float* As = smem[buf];
        const float* Bp = smem[buf] + 1152;

#pragma unroll
        for (int q = 0; q < 32; q += 8) {
            unsigned a[2][4], b[2][2];
#pragma unroll
            for (int mt = 0; mt < 2; mt++) {
                int row = mt * 16 + grp;
                const unsigned* ap  = reinterpret_cast<const unsigned*>(&As[row * 36 + q + th]);
                const unsigned* ap8 = reinterpret_cast<const unsigned*>(&As[(row + 8) * 36 + q + th]);
                a[mt][0] = ap[0];
                a[mt][1] = ap8[0];
                a[mt][2] = ap[4];
                a[mt][3] = ap8[4];
            }
#pragma unroll
            for (int fn = 0; fn < 2; fn++) {
                int col = wid * 16 + fn * 8 + grp;
                if (TB) {
                    const unsigned* bp = reinterpret_cast<const unsigned*>(&Bp[col * 36 + q + th]);
                    b[fn][0] = bp[0];
                    b[fn][1] = bp[4];
                } else {
                    b[fn][0] = reinterpret_cast<const unsigned*>(&Bp[(q + th) * 72 + col])[0];
                    b[fn][1] = reinterpret_cast<const unsigned*>(&Bp[(q + th + 4) * 72 + col])[0];
                }
            }
#pragma unroll
            for (int mt = 0; mt < 2; mt++)
#pragma unroll
                for (int fn = 0; fn < 2; fn++) {
                    asm volatile(
                        "mma.sync.aligned.m16n8k8.row.col.f32.tf32.tf32.f32 "
                        "{%0,%1,%2,%3}, {%4,%5,%6,%7}, {%8,%9}, {%0,%1,%2,%3};"
                        : "+f"(c[mt][fn][0]), "+f"(c[mt][fn][1]),
                          "+f"(c[mt][fn][2]), "+f"(c[mt][fn][3])
                        : "r"(a[mt][0]), "r"(a[mt][1]), "r"(a[mt][2]), "r"(a[mt][3]),
                          "r"(b[fn][0]), "r"(b[fn][1]));
                }
        }
        __syncthreads();
    }

    long base = (long)z * zOut + (long)s * sOut;
#pragma unroll
    for (int mt = 0; mt < 2; mt++) {
        int r0 = mt * 16 + grp;
#pragma unroll
        for (int fn = 0; fn < 2; fn++) {
            int col = n0 + wid * 16 + fn * 8 + th * 2;
            if (col < N) {
                *reinterpret_cast<float2*>(&P[base + (long)r0 * ldcOut + col]) =
                    make_float2(c[mt][fn][0], c[mt][fn][1]);
                if (mt == 0)
                    *reinterpret_cast<float2*>(&P[base + (long)(r0 + 8) * ldcOut + col]) =
                        make_float2(c[mt][fn][2], c[mt][fn][3]);
            }
        }
    }
}

// ------------------------- big tf32 mma GEMM (M=96, 3-stage pipeline) --------
template<bool TB>
__global__ __launch_bounds__(TPB) void mma_gemm(
    const float* __restrict__ A, long Az,
    const float* __restrict__ B, long Bz,
    float* __restrict__ P, int N, int K, int SK,
    const int* __restrict__ patchStart)
{
    extern __shared__ float smem[];
    const int z = blockIdx.z, s = blockIdx.y;
    const int n0 = blockIdx.x * 64;
    const int kLen = K / SK;
    const int kBeg = s * kLen;
    A += (long)z * Az;
    B += (long)z * Bz + (long)patchStart[z] * DIM;

    const int tid  = threadIdx.x;
    const int wid  = tid >> 5;
    const int lane = tid & 31;
    const int grp  = lane >> 2;
    const int th   = lane & 3;
    const int warpM = wid >> 2;
    const int warpN = wid & 3;

    auto load_tile = [&](int t, int buf) {
        float* As = smem + buf * STG;
        float* Bp = smem + buf * STG + 3456;
        const int k0 = kBeg + t * 32;
#pragma unroll
        for (int it = 0; it < 3; it++) {
            int idx = tid + it * TPB;
            int m = idx >> 3, kc = idx & 7;
            cp16(&As[m * 36 + kc * 4], A + (long)m * K + k0 + kc * 4, true);
        }
        if (TB) {
#pragma unroll
            for (int it = 0; it < 2; it++) {
                int idx = tid + it * TPB;
                int nn = idx >> 3, kc = idx & 7;
                cp16(&Bp[nn * 36 + kc * 4], B + (long)(n0 + nn) * DIM + k0 + kc * 4, true);
            }
        } else {
#pragma unroll
            for (int it = 0; it < 2; it++) {
                int idx = tid + it * TPB;
                int kk = idx >> 4, nc = idx & 15;
                cp16(&Bp[kk * 72 + nc * 4], B + (long)(k0 + kk) * DIM + n0 + nc * 4, true);
            }
        }
        cp_commit();
    };

    float c[3][2][4];
#pragma unroll
    for (int i = 0; i < 3; i++)
#pragma unroll
        for (int j = 0; j < 2; j++)
#pragma unroll
            for (int r = 0; r < 4; r++) c[i][j][r] = 0.f;

    const int nT = kLen / 32;
    load_tile(0, 0);
    if (nT > 1) load_tile(1, 1);
    for (int t = 0; t < nT; t++) {
        const int buf = t % 3;
        if (t + 2 < nT) load_tile(t + 2, (t + 2) % 3);
        int ahead = nT - 1 - t;
        if (ahead >= 2)      cp_wait<2>();
        else if (ahead == 1) cp_wait<1>();
        else                 cp_wait<0>();
        __syncthreads();

        const float* As = smem + buf * STG;
        const float* Bp = smem + buf * STG + 3456;

#pragma unroll
        for (int q = 0; q < 32; q += 8) {
            unsigned a[3][4], b[2][2];
#pragma unroll
            for (int fr = 0; fr < 3; fr++) {
                int row = warpM * 48 + fr * 16 + grp;
                const unsigned* ap  = reinterpret_cast<const unsigned*>(&As[row * 36 + q + th]);
                const unsigned* ap8 = reinterpret_cast<const unsigned*>(&As[(row + 8) * 36 + q + th]);
                a[fr][0] = ap[0];
                a[fr][1] = ap8[0];
                a[fr][2] = ap[4];
                a[fr][3] = ap8[4];
            }
#pragma unroll
            for (int fn = 0; fn < 2; fn++) {
                int col = warpN * 16 + fn * 8 + grp;
                if (TB) {
                    const unsigned* bp = reinterpret_cast<const unsigned*>(&Bp[col * 36 + q + th]);
                    b[fn][0] = bp[0];
                    b[fn][1] = bp[4];
                } else {
                    b[fn][0] = reinterpret_cast<const unsigned*>(&Bp[(q + th) * 72 + col])[0];
                    b[fn][1] = reinterpret_cast<const unsigned*>(&Bp[(q + th + 4) * 72 + col])[0];
                }
            }
#pragma unroll
            for (int fr = 0; fr < 3; fr++)
#pragma unroll
                for (int fn = 0; fn < 2; fn++) {
                    asm volatile(
                        "mma.sync.aligned.m16n8k8.row.col.f32.tf32.tf32.f32 "
                        "{%0,%1,%2,%3}, {%4,%5,%6,%7}, {%8,%9}, {%0,%1,%2,%3};"
                        : "+f"(c[fr][fn][0]), "+f"(c[fr][fn][1]),
                          "+f"(c[fr][fn][2]), "+f"(c[fr][fn][3])
                        : "r"(a[fr][0]), "r"(a[fr][1]), "r"(a[fr][2]), "r"(a[fr][3]),
                          "r"(b[fn][0]), "r"(b[fn][1]));
                }
        }
        __syncthreads();
    }

    long base = (long)(z * SK + s) * 96 * N;
#pragma unroll
    for (int fr = 0; fr < 3; fr++) {
        int r0 = warpM * 48 + fr * 16 + grp;
#pragma unroll
        for (int fn = 0; fn < 2; fn++) {
            int col = n0 + warpN * 16 + fn * 8 + th * 2;
            *reinterpret_cast<float2*>(&P[base + (long)r0 * N + col]) =
                make_float2(c[fr][fn][0], c[fr][fn][1]);
            *reinterpret_cast<float2*>(&P[base + (long)(r0 + 8) * N + col]) =
                make_float2(c[fr][fn][2], c[fr][fn][3]);
        }
    }
}

// reduce split-K partials + epilogue
__global__ void combine_kernel(const float* __restrict__ P, int SK,
                               float* __restrict__ C, int ldc, long Cz, int M, int N,
                               const float* __restrict__ bias, long biasZ,
                               const float* __restrict__ resid, long residZ,
                               float scale, int act, int total) {
    int idx = blockIdx.x * blockDim.x + threadIdx.x;
    if (idx >= total) return;
    int n = idx % N;
    int t = idx / N;
    int m = t % M;
    int z = t / M;
    float v = 0.f;
    for (int s = 0; s < SK; s++) v += P[((long)(z * SK + s) * M + m) * N + n];
    if (bias)  v += bias[z * biasZ + n];
    v *= scale;
    if (act)   v = v * normcdff(v);
    if (resid) v += resid[z * residZ + (long)m * ldc + n];
    C[z * Cz + (long)m * ldc + n] = v;
}

// ------------------------- masked softmax (fuses score split-K reduce) -------
__global__ void softmax_kernel(const float* __restrict__ P,
                               float* __restrict__ attn,
                               const float* __restrict__ boxes,
                               const int* __restrict__ thw) {
    int blk = blockIdx.x;
    int b = blk / (NBOX * NHD);
    int n = (blk / NHD) % NBOX;
    int h = blk % NHD;
    int m = n * NHD + h;
    int hg = thw[1], wg = thw[2];
    const float* bx = boxes + (long)(b * NBOX + n) * 4;
    float x1 = bx[0], y1 = bx[1], x2 = bx[2], y2 = bx[3];
    int px1 = min(max((int)floorf(x1 * (float)wg), 0), wg - 1);
    int px2 = max(px1 + 1, min((int)floorf(x2 * (float)wg), wg));
    int py1 = min(max((int)floorf(y1 * (float)hg), 0), hg - 1);
    int py2 = max(py1 + 1, min((int)floorf(y2 * (float)hg), hg));

    const float* r0 = P + ((long)(b * 4 + 0) * 96 + m) * NPATCH;
    const float* r1 = P + ((long)(b * 4 + 1) * 96 + m) * NPATCH;
    const float* r2 = P + ((long)(b * 4 + 2) * 96 + m) * NPATCH;
    const float* r3 = P + ((long)(b * 4 + 3) * 96 + m) * NPATCH;
    float* orow = attn + (long)blk * NPATCH;

    __shared__ float sh[NPATCH];
    __shared__ float red[TPB];
    int tid = threadIdx.x;
    int hw = hg * wg;

    float mx = -1e30f;
    for (int i = tid; i < NPATCH; i += TPB) {
        int q = i % hw;
        int rr = q / wg, cc = q % wg;
        bool in = (rr >= py1) && (rr < py2) && (cc >= px1) && (cc < px2);
        float v = in ? (r0[i] + r1[i] + r2[i] + r3[i]) : -1e30f;
        sh[i] = v;
        mx = fmaxf(mx, v);
    }
    red[tid] = mx;
    __syncthreads();
    for (int s = TPB / 2; s > 0; s >>= 1) {
        if (tid < s) red[tid] = fmaxf(red[tid], red[tid + s]);
        __syncthreads();
    }
    float maxv = red[0];
    __syncthreads();

    float sum = 0.f;
    for (int i = tid; i < NPATCH; i += TPB) {
        float e = expf(sh[i] - maxv);
        sh[i] = e;
        sum += e;
    }
    red[tid] = sum;
    __syncthreads();
    for (int s = TPB / 2; s > 0; s >>= 1) {
        if (tid < s) red[tid] += red[tid + s];
        __syncthreads();
    }
    float inv = 1.f / red[0];
    __syncthreads();
    for (int i = tid; i < NPATCH; i += TPB) orow[i] = sh[i] * inv;
}

// ------------------------- layernorm (fuses combined split-K reduce) ---------
__global__ void ln_fused_kernel(const float* __restrict__ P,
                                const float* __restrict__ bout,
                                const float* __restrict__ gamma,
                                const float* __restrict__ beta) {
    int r = blockIdx.x;
    __shared__ float red[TPB];
    __shared__ float red2[TPB];
    int tid = threadIdx.x;
    float s = 0.f, s2 = 0.f;
    for (int i = tid; i < DIM; i += TPB) {
        float v = bout[i] + g_qtok[(long)r * DIM + i];
#pragma unroll
        for (int k = 0; k < 16; k++)
            v += P[((long)(k * NTOK) + r) * DIM + i];
        g_comb[(long)r * DIM + i] = v;
        s += v;
        s2 += v * v;
    }
    red[tid] = s; red2[tid] = s2;
    __syncthreads();
    for (int st = TPB / 2; st > 0; st >>= 1) {
        if (tid < st) { red[tid] += red[tid + st]; red2[tid] += red2[tid + st]; }
        __syncthreads();
    }
    float mu = red[0] / DIM;
    float var = red2[0] / DIM - mu * mu;
    float inv = rsqrtf(var + 1e-5f);
    for (int i = tid; i < DIM; i += TPB)
        g_ln[(long)r * DIM + i] = (g_comb[(long)r * DIM + i] - mu) * inv * gamma[i] + beta[i];
}

// ------------------------- host tensormap helper -----------------------------
typedef CUresult (*EncodeFn)(
    CUtensorMap*, CUtensorMapDataType, cuuint32_t, void*,
    const cuuint64_t*, const cuuint64_t*, const cuuint32_t*, const cuuint32_t*,
    CUtensorMapInterleave, CUtensorMapSwizzle, CUtensorMapL2promotion,
    CUtensorMapFloatOOBfill);

static void encode_map(EncodeFn fn, CUtensorMap* m, void* ptr,
                       unsigned long long width, unsigned long long height,
                       unsigned long long strideBytes,
                       unsigned boxW, unsigned boxH) {
    cuuint64_t dims[2]    = { width, height };
    cuuint64_t strides[1] = { strideBytes };
    cuuint32_t box[2]     = { boxW, boxH };
    cuuint32_t es[2]      = { 1, 1 };
    fn(m, CU_TENSOR_MAP_DATA_TYPE_FLOAT32, 2, ptr, dims, strides, box, es,
       CU_TENSOR_MAP_INTERLEAVE_NONE, CU_TENSOR_MAP_SWIZZLE_128B,
       CU_TENSOR_MAP_L2_PROMOTION_L2_128B, CU_TENSOR_MAP_FLOAT_OOB_FILL_NONE);
}

// ------------------------- launch --------------------------------------------
extern "C" void kernel_launch(void* const* d_in, const int* in_sizes, int n_in,
                              void* d_out, int out_size) {
    const float*         emb   = (const float*)d_in[0];
    const int*           ids   = (const int*)d_in[1];
    const unsigned char* msk   = (const unsigned char*)d_in[2];
    const float*         boxes = (const float*)d_in[3];
    const int*           thw   = (const int*)d_in[4];
    const int*           tok   = (const int*)d_in[5];
    const float*         Win   = (const float*)d_in[6];
    const float*         bin   = (const float*)d_in[7];
    const float*         Wout  = (const float*)d_in[8];
    const float*         bout  = (const float*)d_in[9];
    const float*         gam   = (const float*)d_in[10];
    const float*         bet   = (const float*)d_in[11];
    const float*         W1    = (const float*)d_in[12];
    const float*         b1    = (const float*)d_in[13];
    const float*         W2    = (const float*)d_in[14];
    const float*         b2    = (const float*)d_in[15];
    float*               out   = (float*)d_out;

    const float* Wq = Win;
    const float* Wk = Win + (long)DIM * DIM;
    const float* Wv = Win + 2L * DIM * DIM;
    const float* bv = bin + 2L * DIM;

    float *qtok, *q, *qk, *scores, *u, *ctx, *ln, *hidden, *rows, *part;
    int *start;
    cudaGetSymbolAddress((void**)&qtok,   g_qtok);
    cudaGetSymbolAddress((void**)&q,      g_q);
    cudaGetSymbolAddress((void**)&qk,     g_qk);
    cudaGetSymbolAddress((void**)&scores, g_scores);
    cudaGetSymbolAddress((void**)&u,      g_u);
    cudaGetSymbolAddress((void**)&ctx,    g_ctx);
    cudaGetSymbolAddress((void**)&ln,     g_ln);
    cudaGetSymbolAddress((void**)&hidden, g_hidden);
    cudaGetSymbolAddress((void**)&rows,   g_rows);
    cudaGetSymbolAddress((void**)&part,   g_part);
    cudaGetSymbolAddress((void**)&start,  g_start);

    cudaFuncSetAttribute(mma_gemm<true>,  cudaFuncAttributeMaxDynamicSharedMemorySize, SMEM_BYTES);
    cudaFuncSetAttribute(mma_gemm<false>, cudaFuncAttributeMaxDynamicSharedMemorySize, SMEM_BYTES);

    // tensormaps for TMA weight streaming
    EncodeFn enc = nullptr;
    cudaGetDriverEntryPoint("cuTensorMapEncodeTiled", (void**)&enc, cudaEnableDefault);
    CUtensorMap mQtok, mU, mCtx, mLn, mHid, mWq, mWv, mWout, mW1, mW2;
    encode_map(enc, &mQtok, qtok,        DIM, NTOK, (unsigned long long)DIM * 4,       32, 24);
    encode_map(enc, &mU,    u,           (unsigned long long)NHD * DIM, NTOK,
                                                    (unsigned long long)NHD * DIM * 4, 32, 24);
    encode_map(enc, &mCtx,  ctx,         DIM, NTOK, (unsigned long long)DIM * 4,       32, 24);
    encode_map(enc, &mLn,   ln,          DIM, NTOK, (unsigned long long)DIM * 4,       32, 24);
    encode_map(enc, &mHid,  hidden,      DFF, NTOK, (unsigned long long)DFF * 4,       32, 24);
    encode_map(enc, &mWq,   (void*)Wq,   DIM, DIM,  (unsigned long long)DIM * 4,       32, 64);
    encode_map(enc, &mWv,   (void*)Wv,   DIM, DIM,  (unsigned long long)DIM * 4,       32, 64);
    encode_map(enc, &mWout, (void*)Wout, DIM, DIM,  (unsigned long long)DIM * 4,       32, 64);
    encode_map(enc, &mW1,   (void*)W1,   DIM, DFF,  (unsigned long long)DIM * 4,       32, 64);
    encode_map(enc, &mW2,   (void*)W2,   DFF, DIM,  (unsigned long long)DFF * 4,       32, 64);

    const float scale = 1.0f / sqrtf((float)DHD);

    // ---- fork: base copy via COPY ENGINE on side stream (zero SM footprint) --
    cudaStream_t s2;
    cudaStreamCreate(&s2);
    cudaEvent_t eFork, eJoin;
    cudaEventCreateWithFlags(&eFork, cudaEventDisableTiming);
    cudaEventCreateWithFlags(&eJoin, cudaEventDisableTiming);
    cudaEventRecord(eFork, 0);
    cudaStreamWaitEvent(s2, eFork, 0);
    cudaMemcpyAsync(out, emb, (size_t)BATCH * SEQ * DIM * sizeof(float),
                    cudaMemcpyDeviceToDevice, s2);
    cudaEventRecord(eJoin, s2);

    // ---- main chain ----
    scan_kernel<<<BATCH, TPB>>>(ids, msk, tok);
    gather_kernel<<<NTOK, TPB>>>(emb);

    // 4. q = (qtok @ Wq^T + bq) * scale   (TMA, SK=16, Kc=224)
    skinny_tma<<<dim3(56, 16, 1), TPBS>>>(mQtok, mWq, 0, 0, part, DIM, DIM, 16);
    combine_kernel<<<(NTOK * DIM + TPB - 1) / TPB, TPB>>>(
        part, 16, q, DIM, 0, NTOK, DIM, bin, 0, nullptr, 0, scale, 0, NTOK * DIM);

    // 5. qk[t,h,:] = q[t,h,:] @ Wk_h   (cp.async NN per head, SK=1, DIRECT write)
    skinny_mma<false><<<dim3(56, 1, NHD), TPBS>>>(q, DIM, DHD, Wk, DIM, (long)DHD * DIM,
                                                  qk, DIM, DHD, 1,
                                                  (long)DIM, 0, NHD * DIM);

    // 6. scores = qk @ patches^T   (SK=4) -> partials consumed by softmax
    mma_gemm<true><<<dim3(NPATCH / 64, 4, BATCH), TPB, SMEM_BYTES>>>(
        qk, (long)96 * DIM, emb, (long)SEQ * DIM,
        part, NPATCH, DIM, 4, start);

    // 7. masked softmax
    softmax_kernel<<<BATCH * NBOX * NHD, TPB>>>(part, scores, boxes, thw);

    // 8. u = attn @ patches   (SK=4)
    mma_gemm<false><<<dim3(DIM / 64, 4, BATCH), TPB, SMEM_BYTES>>>(
        scores, (long)96 * NPATCH, emb, (long)SEQ * DIM,
        part, DIM, NPATCH, 4, start);
    combine_kernel<<<(BATCH * 96 * DIM + TPB - 1) / TPB, TPB>>>(
        part, 4, u, DIM, (long)96 * DIM, 96, DIM,
        nullptr, 0, nullptr, 0, 1.f, 0, BATCH * 96 * DIM);

    // 9. ctx[:, h] = u_h @ Wv_h^T + bv_h   (TMA per head)
    skinny_tma<<<dim3(7, 16, NHD), TPBS>>>(mU, mWv, DIM, DHD, part, DHD, DIM, 16);
    combine_kernel<<<(NHD * NTOK * DHD + TPB - 1) / TPB, TPB>>>(
        part, 16, ctx, DIM, DHD, NTOK, DHD, bv, DHD, nullptr, 0, 1.f, 0,
        NHD * NTOK * DHD);

    // 10. combined partials = ctx @ Wout^T   (TMA, SK=16) -> ln_fused
    skinny_tma<<<dim3(56, 16, 1), TPBS>>>(mCtx, mWout, 0, 0, part, DIM, DIM, 16);

    // 11. layernorm (reduces 16 partials + bout + qtok residual)
    ln_fused_kernel<<<NTOK, TPB>>>(part, bout, gam, bet);

    // 12. hidden = gelu(ln @ W1^T + b1)   (TMA, SK=8, Kc=448)
    skinny_tma<<<dim3(112, 8, 1), TPBS>>>(mLn, mW1, 0, 0, part, DFF, DIM, 8);
    combine_kernel<<<(NTOK * DFF + TPB - 1) / TPB, TPB>>>(
        part, 8, hidden, DFF, 0, NTOK, DFF, b1, 0, nullptr, 0, 1.f, 1, NTOK * DFF);

    // 13. rows = ln + hidden @ W2^T + b2   (TMA, SK=16, Kc=448)
    skinny_tma<<<dim3(56, 16, 1), TPBS>>>(mHid, mW2, 0, 0, part, DIM, DFF, 16);
    combine_kernel<<<(NTOK * DIM + TPB - 1) / TPB, TPB>>>(
        part, 16, rows, DIM, 0, NTOK, DIM, b2, 0, ln, 0, 1.f, 0, NTOK * DIM);

    // ---- join: copy must complete before scatter ----
    cudaStreamWaitEvent(0, eJoin, 0);
    scatter_kernel<<<NTOK, TPB>>>(out);
}

// round 14
// speedup vs baseline: 1.0652x; 1.0361x over previous
#include <cuda_runtime.h>
#include <cuda.h>
#include <math.h>

#define BATCH   2
#define SEQ     4608
#define DIM     3584
#define NHD     8
#define DHD     448
#define NPATCH  4096
#define NBOX    12
#define DFF     7168
#define NTOK    24
#define TPB     256
#define TPBS    128

#define STG     5760        // floats per stage (big mma)
#define SMEM_BYTES (3 * STG * 4)
#define SSTG    3456        // floats per stage (skinny cp.async mma)

// ------------------------- scratch ------------------------------------------
__device__ int   g_pos[NTOK];
__device__ int   g_start[BATCH];
__device__ float g_qtok[NTOK * DIM];
__device__ float g_q[NTOK * DIM];
__device__ float g_qk[NTOK * NHD * DIM];
__device__ float g_scores[BATCH * NBOX * NHD * NPATCH];
__device__ float g_u[NTOK * NHD * DIM];
__device__ float g_ctx[NTOK * DIM];
__device__ float g_comb[NTOK * DIM];
__device__ float g_ln[NTOK * DIM];
__device__ float g_hidden[NTOK * DFF];
__device__ float g_rows[NTOK * DIM];
__device__ float g_part[5505024];          // split-K partial scratch (22 MB)

// ------------------------- cp.async helpers ----------------------------------
__device__ __forceinline__ void cp16(void* smem, const void* gmem, bool pred) {
    unsigned sa = (unsigned)__cvta_generic_to_shared(smem);
    int sz = pred ? 16 : 0;
    asm volatile("cp.async.cg.shared.global [%0], [%1], 16, %2;\n"
                 :: "r"(sa), "l"(gmem), "r"(sz));
}
__device__ __forceinline__ void cp_commit() {
    asm volatile("cp.async.commit_group;\n");
}
template<int NWAIT>
__device__ __forceinline__ void cp_wait() {
    asm volatile("cp.async.wait_group %0;\n" :: "n"(NWAIT));
}

__device__ __forceinline__ void mbar_wait(unsigned mb, int phase) {
    asm volatile(
        "{\n\t.reg .pred P;\n\t"
        "WL_%=:\n\t"
        "mbarrier.try_wait.parity.acquire.cta.shared::cta.b64 P, [%0], %1, 0x989680;\n\t"
        "@P bra WD_%=;\n\t"
        "bra WL_%=;\n\t"
        "WD_%=:\n\t}"
        :: "r"(mb), "r"(phase) : "memory");
}

// ------------------------- simple kernels ------------------------------------
__global__ void scan_kernel(const int* __restrict__ ids,
                            const unsigned char* __restrict__ mask,
                            const int* __restrict__ tokPtr) {
    int b = blockIdx.x;
    __shared__ int sh[SEQ];
    __shared__ int s_f0, s_es, s_off, s_first;
    int tid = threadIdx.x;

    if (tid == 0) s_f0 = 0x7fffffff;
    __syncthreads();
    for (int i = tid; i < SEQ; i += blockDim.x) {
        if (mask[i] != 0) { atomicMin(&s_f0, i); break; }
    }
    __syncthreads();
    if (tid == 0) {
        int f0 = s_f0;
        unsigned char b0 = mask[f0];
        unsigned char b1 = mask[f0 + 1];
        if (b0 == 1u && b1 == 0u)      { s_es = 4; s_off = 0; }
        else if (b0 == 0x80u)          { s_es = 4; s_off = 2; }
        else                           { s_es = 1; s_off = 0; }
        s_first = SEQ;
    }
    __syncthreads();
    int es = s_es, off = s_off;
    for (int i = tid; i < SEQ; i += blockDim.x)
        if (mask[((long)b * SEQ + i) * es + off] != 0) atomicMin(&s_first, i);
    __syncthreads();
    if (tid == 0) g_start[b] = s_first;

    for (int i = tid; i < SEQ; i += blockDim.x)
        sh[i] = ids[(long)b * SEQ + i];
    __syncthreads();
    if (tid < 32) {
        int tok = *tokPtr;
        int count = 0;
        for (int base = 0; base < SEQ && count < NBOX; base += 32) {
            unsigned bal = __ballot_sync(0xffffffffu, sh[base + tid] == tok);
            while (bal && count < NBOX) {
                int o = __ffs(bal) - 1;
                if (tid == 0) g_pos[b * NBOX + count] = base + o;
                count++;
                bal &= bal - 1;
            }
        }
    }
}

__global__ void gather_kernel(const float* __restrict__ emb) {
    int r = blockIdx.x;
    int b = r / NBOX;
    const float* src = emb + ((long)b * SEQ + g_pos[r]) * DIM;
    for (int i = threadIdx.x; i < DIM; i += blockDim.x) g_qtok[(long)r * DIM + i] = src[i];
}

__global__ void scatter_kernel(float* __restrict__ out) {
    int r = blockIdx.x;
    int b = r / NBOX;
    float* dst = out + ((long)b * SEQ + g_pos[r]) * DIM;
    for (int i = threadIdx.x; i < DIM; i += blockDim.x) dst[i] = g_rows[(long)r * DIM + i];
}

// ------------------------- skinny TMA tf32 mma GEMM (TB, 2-stage) ------------
__global__ __launch_bounds__(TPBS) void skinny_tma(
    const __grid_constant__ CUtensorMap mapA,
    const __grid_constant__ CUtensorMap mapW,
    int zxA, int zyW,
    float* __restrict__ P, int N, int K, int SK)
{
    __shared__ __align__(1024) unsigned char sm[2 * 12288];
    __shared__ unsigned long long mbar[2];

    const int z = blockIdx.z, s = blockIdx.y;
    const int n0 = blockIdx.x * 64;
    const int Kc = K / SK;
    const int kBeg = s * Kc;
    const int nT = Kc / 32;

    const int tid  = threadIdx.x;
    const int wid  = tid >> 5;
    const int lane = tid & 31;
    const int grp  = lane >> 2;
    const int th   = lane & 3;

    unsigned smU = (unsigned)__cvta_generic_to_shared(sm);
    unsigned mbU = (unsigned)__cvta_generic_to_shared(mbar);

    if (tid == 0) {
        asm volatile("mbarrier.init.shared.b64 [%0], 1;" :: "r"(mbU) : "memory");
        asm volatile("mbarrier.init.shared.b64 [%0], 1;" :: "r"(mbU + 8) : "memory");
    }
    __syncthreads();

    auto issue = [&](int t, int buf) {
        unsigned mb = mbU + buf * 8;
        asm volatile("mbarrier.arrive.expect_tx.shared.b64 _, [%0], %1;"
                     :: "r"(mb), "r"(11264u) : "memory");
        int x = kBeg + t * 32;
        unsigned aA = smU + buf * 12288;
        unsigned aB = aA + 4096;
        asm volatile(
            "cp.async.bulk.tensor.2d.shared::cta.global.tile.mbarrier::complete_tx::bytes "
            "[%0], [%1, {%2, %3}], [%4];"
            :: "r"(aA), "l"(&mapA), "r"(zxA * z + x), "r"(0), "r"(mb) : "memory");
        asm volatile(
            "cp.async.bulk.tensor.2d.shared::cta.global.tile.mbarrier::complete_tx::bytes "
            "[%0], [%1, {%2, %3}], [%4];"
            :: "r"(aB), "l"(&mapW), "r"(x), "r"(zyW * z + n0), "r"(mb) : "memory");
    };

    if (tid == 0) { issue(0, 0); issue(1, 1); }

    float c[2][2][4];
#pragma unroll
    for (int i = 0; i < 2; i++)
#pragma unroll
        for (int j = 0; j < 2; j++)
#pragma unroll
            for (int r = 0; r < 4; r++) c[i][j][r] = 0.f;

    int ph0 = 0, ph1 = 0;
    const unsigned cx = (unsigned)(grp << 4);   // SW128 col-xor

    for (int t = 0; t < nT; t++) {
        const int buf = t & 1;
        if (buf == 0) { mbar_wait(mbU, ph0); ph0 ^= 1; }
        else          { mbar_wait(mbU + 8, ph1); ph1 ^= 1; }

        const unsigned char* base = sm + buf * 12288;
        const unsigned char* aT = base;
        const unsigned char* bT = base + 4096;

#pragma unroll
        for (int q = 0; q < 32; q += 8) {
            unsigned c0 = ((unsigned)((q + th) * 4)) ^ cx;
            unsigned c1 = ((unsigned)((q + th + 4) * 4)) ^ cx;
            unsigned a[2][4], b[2][2];
#pragma unroll
            for (int mt = 0; mt < 2; mt++) {
                int r = mt * 16 + grp;
                a[mt][0] = *(const unsigned*)(aT + r * 128 + c0);
                a[mt][1] = *(const unsigned*)(aT + (r + 8) * 128 + c0);
                a[mt][2] = *(const unsigned*)(aT + r * 128 + c1);
                a[mt][3] = *(const unsigned*)(aT + (r + 8) * 128 + c1);
            }
#pragma unroll
            for (int fn = 0; fn < 2; fn++) {
                int col = wid * 16 + fn * 8 + grp;
                b[fn][0] = *(const unsigned*)(bT + col * 128 + c0);
                b[fn][1] = *(const unsigned*)(bT + col * 128 + c1);
            }
#pragma unroll
            for (int mt = 0; mt < 2; mt++)
#pragma unroll
                for (int fn = 0; fn < 2; fn++) {
                    asm volatile(
                        "mma.sync.aligned.m16n8k8.row.col.f32.tf32.tf32.f32 "
                        "{%0,%1,%2,%3}, {%4,%5,%6,%7}, {%8,%9}, {%0,%1,%2,%3};"
                        : "+f"(c[mt][fn][0]), "+f"(c[mt][fn][1]),
                          "+f"(c[mt][fn][2]), "+f"(c[mt][fn][3])
                        : "r"(a[mt][0]), "r"(a[mt][1]), "r"(a[mt][2]), "r"(a[mt][3]),
                          "r"(b[fn][0]), "r"(b[fn][1]));
                }
        }
        __syncthreads();
        if (t + 2 < nT && tid == 0) issue(t + 2, buf);
    }

    long base2 = (long)(z * SK + s) * NTOK * N;
#pragma unroll
    for (int mt = 0; mt < 2; mt++) {
        int r0 = mt * 16 + grp;
#pragma unroll
        for (int fn = 0; fn < 2; fn++) {
            int col = n0 + wid * 16 + fn * 8 + th * 2;
            *reinterpret_cast<float2*>(&P[base2 + (long)r0 * N + col]) =
                make_float2(c[mt][fn][0], c[mt][fn][1]);
            if (mt == 0)
                *reinterpret_cast<float2*>(&P[base2 + (long)(r0 + 8) * N + col]) =
                    make_float2(c[mt][fn][2], c[mt][fn][3]);
        }
    }
}

// ------------------------- skinny cp.async tf32 mma GEMM (NN) ----------------
template<bool TB>
__global__ __launch_bounds__(TPBS) void skinny_mma(
    const float* __restrict__ A, int lda, long Az,
    const float* __restrict__ W, int ldw, long Wz,
    float* __restrict__ P, int N, int K, int SK,
    long zOut, long sOut, int ldcOut)
{
    __shared__ float smem[2][SSTG];
    const int z = blockIdx.z, s = blockIdx.y;
    const int n0 = blockIdx.x * 64;
    const int Kc = K / SK;
    const int kBeg = s * Kc;
    A += (long)z * Az;
    W += (long)z * Wz;

    const int tid  = threadIdx.x;
    const int wid  = tid >> 5;
    const int lane = tid & 31;
    const int grp  = lane >> 2;
    const int th   = lane & 3;

    auto load_tile = [&](int t, int buf) {
        float* As = smem[buf];
        float* Bp = smem[buf] + 1152;
        const int k0 = kBeg + t * 32;
#pragma unroll
        for (int it = 0; it < 2; it++) {
            int idx = tid + it * TPBS;
            int m = idx >> 3, kc = idx & 7;
            cp16(&As[m * 36 + kc * 4], A + (long)m * lda + k0 + kc * 4, m < NTOK);
        }
        if (TB) {
#pragma unroll
            for (int it = 0; it < 4; it++) {
                int idx = tid + it * TPBS;
                int nn = idx >> 3, kc = idx & 7;
                cp16(&Bp[nn * 36 + kc * 4],
                     W + (long)(n0 + nn) * ldw + k0 + kc * 4, n0 + nn < N);
            }
        } else {
#pragma unroll
            for (int it = 0; it < 4; it++) {
                int idx = tid + it * TPBS;
                int kk = idx >> 4, nc = idx & 15;
                cp16(&Bp[kk * 72 + nc * 4],
                     W + (long)(k0 + kk) * ldw + n0 + nc * 4, n0 + nc * 4 < N);
            }
        }
        cp_commit();
    };

    float c[2][2][4];
#pragma unroll
    for (int i = 0; i < 2; i++)
#pragma unroll
        for (int j = 0; j < 2; j++)
#pragma unroll
            for (int r = 0; r < 4; r++) c[i][j][r] = 0.f;

    const int nT = Kc / 32;
    load_tile(0, 0);
    for (int t = 0; t < nT; t++) {
        const int buf = t & 1;
        if (t + 1 < nT) { load_tile(t + 1, buf ^ 1); cp_wait<1>(); }
        else            { cp_wait<0>(); }
        __syncthreads();

        const float* As = smem[buf];
        const float* Bp = smem[buf] + 1152;

#pragma unroll
        for (int q = 0; q < 32; q += 8) {
            unsigned a[2][4], b[2][2];
#pragma unroll
            for (int mt = 0; mt < 2; mt++) {
                int row = mt * 16 + grp;
                const unsigned* ap  = reinterpret_cast<const unsigned*>(&As[row * 36 + q + th]);
                const unsigned* ap8 = reinterpret_cast<const unsigned*>(&As[(row + 8) * 36 + q + th]);
                a[mt][0] = ap[0];
                a[mt][1] = ap8[0];
                a[mt][2] = ap[4];
                a[mt][3] = ap8[4];
            }
#pragma unroll
            for (int fn = 0; fn < 2; fn++) {
                int col = wid * 16 + fn * 8 + grp;
                if (TB) {
                    const unsigned* bp = reinterpret_cast<const unsigned*>(&Bp[col * 36 + q + th]);
                    b[fn][0] = bp[0];
                    b[fn][1] = bp[4];
                } else {
                    b[fn][0] = reinterpret_cast<const unsigned*>(&Bp[(q + th) * 72 + col])[0];
                    b[fn][1] = reinterpret_cast<const unsigned*>(&Bp[(q + th + 4) * 72 + col])[0];
                }
            }
#pragma unroll
            for (int mt = 0; mt < 2; mt++)
#pragma unroll
                for (int fn = 0; fn < 2; fn++) {
                    asm volatile(
                        "mma.sync.aligned.m16n8k8.row.col.f32.tf32.tf32.f32 "
                        "{%0,%1,%2,%3}, {%4,%5,%6,%7}, {%8,%9}, {%0,%1,%2,%3};"
                        : "+f"(c[mt][fn][0]), "+f"(c[mt][fn][1]),
                          "+f"(c[mt][fn][2]), "+f"(c[mt][fn][3])
                        : "r"(a[mt][0]), "r"(a[mt][1]), "r"(a[mt][2]), "r"(a[mt][3]),
                          "r"(b[fn][0]), "r"(b[fn][1]));
                }
        }
        __syncthreads();
    }

    long base = (long)z * zOut + (long)s * sOut;
#pragma unroll
    for (int mt = 0; mt < 2; mt++) {
        int r0 = mt * 16 + grp;
#pragma unroll
        for (int fn = 0; fn < 2; fn++) {
            int col = n0 + wid * 16 + fn * 8 + th * 2;
            if (col < N) {
                *reinterpret_cast<float2*>(&P[base + (long)r0 * ldcOut + col]) =
                    make_float2(c[mt][fn][0], c[mt][fn][1]);
                if (mt == 0)
                    *reinterpret_cast<float2*>(&P[base + (long)(r0 + 8) * ldcOut + col]) =
                        make_float2(c[mt][fn][2], c[mt][fn][3]);
            }
        }
    }
}

// ------------------------- big tf32 mma GEMM (M=96, 3-stage pipeline) --------
template<bool TB>
__global__ __launch_bounds__(TPB) void mma_gemm(
    const float* __restrict__ A, long Az,
    const float* __restrict__ B, long Bz,
    float* __restrict__ P, int N, int K, int SK,
    const int* __restrict__ patchStart)
{
    extern __shared__ float smem[];
    const int z = blockIdx.z, s = blockIdx.y;
    const int n0 = blockIdx.x * 64;
    const int kLen = K / SK;
    const int kBeg = s * kLen;
    A += (long)z * Az;
    B += (long)z * Bz + (long)patchStart[z] * DIM;

    const int tid  = threadIdx.x;
    const int wid  = tid >> 5;
    const int lane = tid & 31;
    const int grp  = lane >> 2;
    const int th   = lane & 3;
    const int warpM = wid >> 2;
    const int warpN = wid & 3;

    auto load_tile = [&](int t, int buf) {
        float* As = smem + buf * STG;
        float* Bp = smem + buf * STG + 3456;
        const int k0 = kBeg + t * 32;
#pragma unroll
        for (int it = 0; it < 3; it++) {
            int idx = tid + it * TPB;
            int m = idx >> 3, kc = idx & 7;
            cp16(&As[m * 36 + kc * 4], A + (long)m * K + k0 + kc * 4, true);
        }
        if (TB) {
#pragma unroll
            for (int it = 0; it < 2; it++) {
                int idx = tid + it * TPB;
                int nn = idx >> 3, kc = idx & 7;
                cp16(&Bp[nn * 36 + kc * 4], B + (long)(n0 + nn) * DIM + k0 + kc * 4, true);
            }
        } else {
#pragma unroll
            for (int it = 0; it < 2; it++) {
                int idx = tid + it * TPB;
                int kk = idx >> 4, nc = idx & 15;
                cp16(&Bp[kk * 72 + nc * 4], B + (long)(k0 + kk) * DIM + n0 + nc * 4, true);
            }
        }
        cp_commit();
    };

    float c[3][2][4];
#pragma unroll
    for (int i = 0; i < 3; i++)
#pragma unroll
        for (int j = 0; j < 2; j++)
#pragma unroll
            for (int r = 0; r < 4; r++) c[i][j][r] = 0.f;

    const int nT = kLen / 32;
    load_tile(0, 0);
    if (nT > 1) load_tile(1, 1);
    for (int t = 0; t < nT; t++) {
        const int buf = t % 3;
        if (t + 2 < nT) load_tile(t + 2, (t + 2) % 3);
        int ahead = nT - 1 - t;
        if (ahead >= 2)      cp_wait<2>();
        else if (ahead == 1) cp_wait<1>();
        else                 cp_wait<0>();
        __syncthreads();

        const float* As = smem + buf * STG;
        const float* Bp = smem + buf * STG + 3456;

#pragma unroll
        for (int q = 0; q < 32; q += 8) {
            unsigned a[3][4], b[2][2];
#pragma unroll
            for (int fr = 0; fr < 3; fr++) {
                int row = warpM * 48 + fr * 16 + grp;
                const unsigned* ap  = reinterpret_cast<const unsigned*>(&As[row * 36 + q + th]);
                const unsigned* ap8 = reinterpret_cast<const unsigned*>(&As[(row + 8) * 36 + q + th]);
                a[fr][0] = ap[0];
                a[fr][1] = ap8[0];
                a[fr][2] = ap[4];
                a[fr][3] = ap8[4];
            }
#pragma unroll
            for (int fn = 0; fn < 2; fn++) {
                int col = warpN * 16 + fn * 8 + grp;
                if (TB) {
                    const unsigned* bp = reinterpret_cast<const unsigned*>(&Bp[col * 36 + q + th]);
                    b[fn][0] = bp[0];
                    b[fn][1] = bp[4];
                } else {
                    b[fn][0] = reinterpret_cast<const unsigned*>(&Bp[(q + th) * 72 + col])[0];
                    b[fn][1] = reinterpret_cast<const unsigned*>(&Bp[(q + th + 4) * 72 + col])[0];
                }
            }
#pragma unroll
            for (int fr = 0; fr < 3; fr++)
#pragma unroll
                for (int fn = 0; fn < 2; fn++) {
                    asm volatile(
                        "mma.sync.aligned.m16n8k8.row.col.f32.tf32.tf32.f32 "
                        "{%0,%1,%2,%3}, {%4,%5,%6,%7}, {%8,%9}, {%0,%1,%2,%3};"
                        : "+f"(c[fr][fn][0]), "+f"(c[fr][fn][1]),
                          "+f"(c[fr][fn][2]), "+f"(c[fr][fn][3])
                        : "r"(a[fr][0]), "r"(a[fr][1]), "r"(a[fr][2]), "r"(a[fr][3]),
                          "r"(b[fn][0]), "r"(b[fn][1]));
                }
        }
        __syncthreads();
    }

    long base = (long)(z * SK + s) * 96 * N;
#pragma unroll
    for (int fr = 0; fr < 3; fr++) {
        int r0 = warpM * 48 + fr * 16 + grp;
#pragma unroll
        for (int fn = 0; fn < 2; fn++) {
            int col = n0 + warpN * 16 + fn * 8 + th * 2;
            *reinterpret_cast<float2*>(&P[base + (long)r0 * N + col]) =
                make_float2(c[fr][fn][0], c[fr][fn][1]);
            *reinterpret_cast<float2*>(&P[base + (long)(r0 + 8) * N + col]) =
                make_float2(c[fr][fn][2], c[fr][fn][3]);
        }
    }
}

// --------- templated combine: compile-time unrolled split-K reduce, float4 ---
template<int SK>
__global__ void combine_kernel(const float* __restrict__ P,
                               float* __restrict__ C, int ldc, long Cz, int M, int N,
                               const float* __restrict__ bias, long biasZ,
                               const float* __restrict__ resid, long residZ,
                               float scale, int act, int total4) {
    int idx = blockIdx.x * blockDim.x + threadIdx.x;
    if (idx >= total4) return;
    int n4 = N >> 2;
    int n = (idx % n4) << 2;
    int t = idx / n4;
    int m = t % M;
    int z = t / M;

    float4 v = make_float4(0.f, 0.f, 0.f, 0.f);
#pragma unroll
    for (int s = 0; s < SK; s++) {
        float4 p = *reinterpret_cast<const float4*>(
            &P[((long)(z * SK + s) * M + m) * N + n]);
        v.x += p.x; v.y += p.y; v.z += p.z; v.w += p.w;
    }
    if (bias) {
        float4 b = *reinterpret_cast<const float4*>(&bias[z * biasZ + n]);
        v.x += b.x; v.y += b.y; v.z += b.z; v.w += b.w;
    }
    v.x *= scale; v.y *= scale; v.z *= scale; v.w *= scale;
    if (act) {
        v.x = v.x * normcdff(v.x);
        v.y = v.y * normcdff(v.y);
        v.z = v.z * normcdff(v.z);
        v.w = v.w * normcdff(v.w);
    }
    if (resid) {
        float4 r = *reinterpret_cast<const float4*>(
            &resid[z * residZ + (long)m * ldc + n]);
        v.x += r.x; v.y += r.y; v.z += r.z; v.w += r.w;
    }
    *reinterpret_cast<float4*>(&C[z * Cz + (long)m * ldc + n]) = v;
}

// ------------------------- masked softmax (fuses score split-K reduce) -------
__global__ void softmax_kernel(const float* __restrict__ P,
                               float* __restrict__ attn,
                               const float* __restrict__ boxes,
                               const int* __restrict__ thw) {
    int blk = blockIdx.x;
    int b = blk / (NBOX * NHD);
    int n = (blk / NHD) % NBOX;
    int h = blk % NHD;
    int m = n * NHD + h;
    int hg = thw[1], wg = thw[2];
    const float* bx = boxes + (long)(b * NBOX + n) * 4;
    float x1 = bx[0], y1 = bx[1], x2 = bx[2], y2 = bx[3];
    int px1 = min(max((int)floorf(x1 * (float)wg), 0), wg - 1);
    int px2 = max(px1 + 1, min((int)floorf(x2 * (float)wg), wg));
    int py1 = min(max((int)floorf(y1 * (float)hg), 0), hg - 1);
    int py2 = max(py1 + 1, min((int)floorf(y2 * (float)hg), hg));

    const float* r0 = P + ((long)(b * 4 + 0) * 96 + m) * NPATCH;
    const float* r1 = P + ((long)(b * 4 + 1) * 96 + m) * NPATCH;
    const float* r2 = P + ((long)(b * 4 + 2) * 96 + m) * NPATCH;
    const float* r3 = P + ((long)(b * 4 + 3) * 96 + m) * NPATCH;
    float* orow = attn + (long)blk * NPATCH;

    __shared__ float sh[NPATCH];
    __shared__ float red[TPB];
    int tid = threadIdx.x;
    int hw = hg * wg;

    float mx = -1e30f;
    for (int i = tid; i < NPATCH; i += TPB) {
        int q = i % hw;
        int rr = q / wg, cc = q % wg;
        bool in = (rr >= py1) && (rr < py2) && (cc >= px1) && (cc < px2);
        float v = in ? (r0[i] + r1[i] + r2[i] + r3[i]) : -1e30f;
        sh[i] = v;
        mx = fmaxf(mx, v);
    }
    red[tid] = mx;
    __syncthreads();
    for (int s = TPB / 2; s > 0; s >>= 1) {
        if (tid < s) red[tid] = fmaxf(red[tid], red[tid + s]);
        __syncthreads();
    }
    float maxv = red[0];
    __syncthreads();

    float sum = 0.f;
    for (int i = tid; i < NPATCH; i += TPB) {
        float e = expf(sh[i] - maxv);
        sh[i] = e;
        sum += e;
    }
    red[tid] = sum;
    __syncthreads();
    for (int s = TPB / 2; s > 0; s >>= 1) {
        if (tid < s) red[tid] += red[tid + s];
        __syncthreads();
    }
    float inv = 1.f / red[0];
    __syncthreads();
    for (int i = tid; i < NPATCH; i += TPB) orow[i] = sh[i] * inv;
}

// ------------------------- layernorm (fuses combined split-K reduce) ---------
__global__ void ln_fused_kernel(const float* __restrict__ P,
                                const float* __restrict__ bout,
                                const float* __restrict__ gamma,
                                const float* __restrict__ beta) {
    int r = blockIdx.x;
    __shared__ float red[TPB];
    __shared__ float red2[TPB];
    int tid = threadIdx.x;
    float s = 0.f, s2 = 0.f;
    for (int i = tid * 4; i < DIM; i += TPB * 4) {
        float4 v = *reinterpret_cast<const float4*>(&bout[i]);
        float4 qv = *reinterpret_cast<const float4*>(&g_qtok[(long)r * DIM + i]);
        v.x += qv.x; v.y += qv.y; v.z += qv.z; v.w += qv.w;
#pragma unroll
        for (int k = 0; k < 16; k++) {
            float4 p = *reinterpret_cast<const float4*>(
                &P[((long)(k * NTOK) + r) * DIM + i]);
            v.x += p.x; v.y += p.y; v.z += p.z; v.w += p.w;
        }
        *reinterpret_cast<float4*>(&g_comb[(long)r * DIM + i]) = v;
        s += v.x + v.y + v.z + v.w;
        s2 += v.x * v.x + v.y * v.y + v.z * v.z + v.w * v.w;
    }
    red[tid] = s; red2[tid] = s2;
    __syncthreads();
    for (int st = TPB / 2; st > 0; st >>= 1) {
        if (tid < st) { red[tid] += red[tid + st]; red2[tid] += red2[tid + st]; }
        __syncthreads();
    }
    float mu = red[0] / DIM;
    float var = red2[0] / DIM - mu * mu;
    float inv = rsqrtf(var + 1e-5f);
    for (int i = tid; i < DIM; i += TPB)
        g_ln[(long)r * DIM + i] = (g_comb[(long)r * DIM + i] - mu) * inv * gamma[i] + beta[i];
}

// ------------------------- host tensormap helper -----------------------------
typedef CUresult (*EncodeFn)(
    CUtensorMap*, CUtensorMapDataType, cuuint32_t, void*,
    const cuuint64_t*, const cuuint64_t*, const cuuint32_t*, const cuuint32_t*,
    CUtensorMapInterleave, CUtensorMapSwizzle, CUtensorMapL2promotion,
    CUtensorMapFloatOOBfill);

static void encode_map(EncodeFn fn, CUtensorMap* m, void* ptr,
                       unsigned long long width, unsigned long long height,
                       unsigned long long strideBytes,
                       unsigned boxW, unsigned boxH) {
    cuuint64_t dims[2]    = { width, height };
    cuuint64_t strides[1] = { strideBytes };
    cuuint32_t box[2]     = { boxW, boxH };
    cuuint32_t es[2]      = { 1, 1 };
    fn(m, CU_TENSOR_MAP_DATA_TYPE_FLOAT32, 2, ptr, dims, strides, box, es,
       CU_TENSOR_MAP_INTERLEAVE_NONE, CU_TENSOR_MAP_SWIZZLE_128B,
       CU_TENSOR_MAP_L2_PROMOTION_L2_128B, CU_TENSOR_MAP_FLOAT_OOB_FILL_NONE);
}

// ------------------------- launch --------------------------------------------
extern "C" void kernel_launch(void* const* d_in, const int* in_sizes, int n_in,
                              void* d_out, int out_size) {
    const float*         emb   = (const float*)d_in[0];
    const int*           ids   = (const int*)d_in[1];
    const unsigned char* msk   = (const unsigned char*)d_in[2];
    const float*         boxes = (const float*)d_in[3];
    const int*           thw   = (const int*)d_in[4];
    const int*           tok   = (const int*)d_in[5];
    const float*         Win   = (const float*)d_in[6];
    const float*         bin   = (const float*)d_in[7];
    const float*         Wout  = (const float*)d_in[8];
    const float*         bout  = (const float*)d_in[9];
    const float*         gam   = (const float*)d_in[10];
    const float*         bet   = (const float*)d_in[11];
    const float*         W1    = (const float*)d_in[12];
    const float*         b1    = (const float*)d_in[13];
    const float*         W2    = (const float*)d_in[14];
    const float*         b2    = (const float*)d_in[15];
    float*               out   = (float*)d_out;

    const float* Wq = Win;
    const float* Wk = Win + (long)DIM * DIM;
    const float* Wv = Win + 2L * DIM * DIM;
    const float* bv = bin + 2L * DIM;

    float *qtok, *q, *qk, *scores, *u, *ctx, *ln, *hidden, *rows, *part;
    int *start;
    cudaGetSymbolAddress((void**)&qtok,   g_qtok);
    cudaGetSymbolAddress((void**)&q,      g_q);
    cudaGetSymbolAddress((void**)&qk,     g_qk);
    cudaGetSymbolAddress((void**)&scores, g_scores);
    cudaGetSymbolAddress((void**)&u,      g_u);
    cudaGetSymbolAddress((void**)&ctx,    g_ctx);
    cudaGetSymbolAddress((void**)&ln,     g_ln);
    cudaGetSymbolAddress((void**)&hidden, g_hidden);
    cudaGetSymbolAddress((void**)&rows,   g_rows);
    cudaGetSymbolAddress((void**)&part,   g_part);
    cudaGetSymbolAddress((void**)&start,  g_start);

    cudaFuncSetAttribute(mma_gemm<true>,  cudaFuncAttributeMaxDynamicSharedMemorySize, SMEM_BYTES);
    cudaFuncSetAttribute(mma_gemm<false>, cudaFuncAttributeMaxDynamicSharedMemorySize, SMEM_BYTES);

    // tensormaps for TMA weight streaming
    EncodeFn enc = nullptr;
    cudaGetDriverEntryPoint("cuTensorMapEncodeTiled", (void**)&enc, cudaEnableDefault);
    CUtensorMap mQtok, mU, mCtx, mLn, mHid, mWq, mWv, mWout, mW1, mW2;
    encode_map(enc, &mQtok, qtok,        DIM, NTOK, (unsigned long long)DIM * 4,       32, 24);
    encode_map(enc, &mU,    u,           (unsigned long long)NHD * DIM, NTOK,
                                                    (unsigned long long)NHD * DIM * 4, 32, 24);
    encode_map(enc, &mCtx,  ctx,         DIM, NTOK, (unsigned long long)DIM * 4,       32, 24);
    encode_map(enc, &mLn,   ln,          DIM, NTOK, (unsigned long long)DIM * 4,       32, 24);
    encode_map(enc, &mHid,  hidden,      DFF, NTOK, (unsigned long long)DFF * 4,       32, 24);
    encode_map(enc, &mWq,   (void*)Wq,   DIM, DIM,  (unsigned long long)DIM * 4,       32, 64);
    encode_map(enc, &mWv,   (void*)Wv,   DIM, DIM,  (unsigned long long)DIM * 4,       32, 64);
    encode_map(enc, &mWout, (void*)Wout, DIM, DIM,  (unsigned long long)DIM * 4,       32, 64);
    encode_map(enc, &mW1,   (void*)W1,   DIM, DFF,  (unsigned long long)DIM * 4,       32, 64);
    encode_map(enc, &mW2,   (void*)W2,   DFF, DIM,  (unsigned long long)DFF * 4,       32, 64);

    const float scale = 1.0f / sqrtf((float)DHD);

    // ---- fork: base copy via copy engine on side stream ----
    cudaStream_t s2;
    cudaStreamCreate(&s2);
    cudaEvent_t eFork, eJoin;
    cudaEventCreateWithFlags(&eFork, cudaEventDisableTiming);
    cudaEventCreateWithFlags(&eJoin, cudaEventDisableTiming);
    cudaEventRecord(eFork, 0);
    cudaStreamWaitEvent(s2, eFork, 0);
    cudaMemcpyAsync(out, emb, (size_t)BATCH * SEQ * DIM * sizeof(float),
                    cudaMemcpyDeviceToDevice, s2);
    cudaEventRecord(eJoin, s2);

    // ---- main chain ----
    scan_kernel<<<BATCH, TPB>>>(ids, msk, tok);
    gather_kernel<<<NTOK, TPB>>>(emb);

    // 4. q = (qtok @ Wq^T + bq) * scale   (TMA, SK=16, Kc=224)
    skinny_tma<<<dim3(56, 16, 1), TPBS>>>(mQtok, mWq, 0, 0, part, DIM, DIM, 16);
    combine_kernel<16><<<(NTOK * DIM / 4 + TPB - 1) / TPB, TPB>>>(
        part, q, DIM, 0, NTOK, DIM, bin, 0, nullptr, 0, scale, 0, NTOK * DIM / 4);

    // 5. qk[t,h,:] = q[t,h,:] @ Wk_h   (cp.async NN per head, SK=1, DIRECT write)
    skinny_mma<false><<<dim3(56, 1, NHD), TPBS>>>(q, DIM, DHD, Wk, DIM, (long)DHD * DIM,
                                                  qk, DIM, DHD, 1,
                                                  (long)DIM, 0, NHD * DIM);

    // 6. scores = qk @ patches^T   (SK=4) -> partials consumed by softmax
    mma_gemm<true><<<dim3(NPATCH / 64, 4, BATCH), TPB, SMEM_BYTES>>>(
        qk, (long)96 * DIM, emb, (long)SEQ * DIM,
        part, NPATCH, DIM, 4, start);

    // 7. masked softmax
    softmax_kernel<<<BATCH * NBOX * NHD, TPB>>>(part, scores, boxes, thw);

    // 8. u = attn @ patches   (SK=4)
    mma_gemm<false><<<dim3(DIM / 64, 4, BATCH), TPB, SMEM_BYTES>>>(
        scores, (long)96 * NPATCH, emb, (long)SEQ * DIM,
        part, DIM, NPATCH, 4, start);
    combine_kernel<4><<<(BATCH * 96 * DIM / 4 + TPB - 1) / TPB, TPB>>>(
        part, u, DIM, (long)96 * DIM, 96, DIM,
        nullptr, 0, nullptr, 0, 1.f, 0, BATCH * 96 * DIM / 4);

    // 9. ctx[:, h] = u_h @ Wv_h^T + bv_h   (TMA per head)
    skinny_tma<<<dim3(7, 16, NHD), TPBS>>>(mU, mWv, DIM, DHD, part, DHD, DIM, 16);
    combine_kernel<16><<<(NHD * NTOK * DHD / 4 + TPB - 1) / TPB, TPB>>>(
        part, ctx, DIM, DHD, NTOK, DHD, bv, DHD, nullptr, 0, 1.f, 0,
        NHD * NTOK * DHD / 4);

    // 10. combined partials = ctx @ Wout^T   (TMA, SK=16) -> ln_fused
    skinny_tma<<<dim3(56, 16, 1), TPBS>>>(mCtx, mWout, 0, 0, part, DIM, DIM, 16);

    // 11. layernorm (reduces 16 partials + bout + qtok residual)
    ln_fused_kernel<<<NTOK, TPB>>>(part, bout, gam, bet);

    // 12. hidden = gelu(ln @ W1^T + b1)   (TMA, SK=8, Kc=448)
    skinny_tma<<<dim3(112, 8, 1), TPBS>>>(mLn, mW1, 0, 0, part, DFF, DIM, 8);
    combine_kernel<8><<<(NTOK * DFF / 4 + TPB - 1) / TPB, TPB>>>(
        part, hidden, DFF, 0, NTOK, DFF, b1, 0, nullptr, 0, 1.f, 1, NTOK * DFF / 4);

    // 13. rows = ln + hidden @ W2^T + b2   (TMA, SK=16, Kc=448)
    skinny_tma<<<dim3(56, 16, 1), TPBS>>>(mHid, mW2, 0, 0, part, DIM, DFF, 16);
    combine_kernel<16><<<(NTOK * DIM / 4 + TPB - 1) / TPB, TPB>>>(
        part, rows, DIM, 0, NTOK, DIM, b2, 0, ln, 0, 1.f, 0, NTOK * DIM / 4);

    // ---- join: copy must complete before scatter ----
    cudaStreamWaitEvent(0, eJoin, 0);
    scatter_kernel<<<NTOK, TPB>>>(out);
}

// round 15
// speedup vs baseline: 1.0662x; 1.0010x over previous
#include <cuda_runtime.h>
#include <cuda.h>
#include <math.h>

#define BATCH   2
#define SEQ     4608
#define DIM     3584
#define NHD     8
#define DHD     448
#define NPATCH  4096
#define NBOX    12
#define DFF     7168
#define NTOK    24
#define TPB     256
#define TPBS    128

#define STG     5760
#define SMEM_BYTES (3 * STG * 4)
#define SSTG    3456

// ------------------------- scratch ------------------------------------------
__device__ int   g_pos[NTOK];
__device__ int   g_start[BATCH];
__device__ float g_qtok[NTOK * DIM];
__device__ float g_q[NTOK * DIM];
__device__ float g_qk[NTOK * NHD * DIM];
__device__ float g_scores[BATCH * NBOX * NHD * NPATCH];
__device__ float g_u[NTOK * NHD * DIM];
__device__ float g_ctx[NTOK * DIM];
__device__ float g_comb[NTOK * DIM];
__device__ float g_ln[NTOK * DIM];
__device__ float g_hidden[NTOK * DFF];
__device__ float g_rows[NTOK * DIM];
__device__ float g_part[5505024];

// ------------------------- cp.async helpers ----------------------------------
__device__ __forceinline__ void cp16(void* smem, const void* gmem, bool pred) {
    unsigned sa = (unsigned)__cvta_generic_to_shared(smem);
    int sz = pred ? 16 : 0;
    asm volatile("cp.async.cg.shared.global [%0], [%1], 16, %2;\n"
                 :: "r"(sa), "l"(gmem), "r"(sz));
}
__device__ __forceinline__ void cp_commit() {
    asm volatile("cp.async.commit_group;\n");
}
template<int NWAIT>
__device__ __forceinline__ void cp_wait() {
    asm volatile("cp.async.wait_group %0;\n" :: "n"(NWAIT));
}

__device__ __forceinline__ void mbar_wait(unsigned mb, int phase) {
    asm volatile(
        "{\n\t.reg .pred P;\n\t"
        "WL_%=:\n\t"
        "mbarrier.try_wait.parity.acquire.cta.shared::cta.b64 P, [%0], %1, 0x989680;\n\t"
        "@P bra WD_%=;\n\t"
        "bra WL_%=;\n\t"
        "WD_%=:\n\t}"
        :: "r"(mb), "r"(phase) : "memory");
}

// ------------------------- simple kernels ------------------------------------
__global__ void scan_kernel(const int* __restrict__ ids,
                            const unsigned char* __restrict__ mask,
                            const int* __restrict__ tokPtr) {
    int b = blockIdx.x;
    __shared__ int sh[SEQ];
    __shared__ int s_f0, s_es, s_off, s_first;
    int tid = threadIdx.x;

    if (tid == 0) s_f0 = 0x7fffffff;
    __syncthreads();
    for (int i = tid; i < SEQ; i += blockDim.x) {
        if (mask[i] != 0) { atomicMin(&s_f0, i); break; }
    }
    __syncthreads();
    if (tid == 0) {
        int f0 = s_f0;
        unsigned char b0 = mask[f0];
        unsigned char b1 = mask[f0 + 1];
        if (b0 == 1u && b1 == 0u)      { s_es = 4; s_off = 0; }
        else if (b0 == 0x80u)          { s_es = 4; s_off = 2; }
        else                           { s_es = 1; s_off = 0; }
        s_first = SEQ;
    }
    __syncthreads();
    int es = s_es, off = s_off;
    for (int i = tid; i < SEQ; i += blockDim.x)
        if (mask[((long)b * SEQ + i) * es + off] != 0) atomicMin(&s_first, i);
    __syncthreads();
    if (tid == 0) g_start[b] = s_first;

    for (int i = tid; i < SEQ; i += blockDim.x)
        sh[i] = ids[(long)b * SEQ + i];
    __syncthreads();
    if (tid < 32) {
        int tok = *tokPtr;
        int count = 0;
        for (int base = 0; base < SEQ && count < NBOX; base += 32) {
            unsigned bal = __ballot_sync(0xffffffffu, sh[base + tid] == tok);
            while (bal && count < NBOX) {
                int o = __ffs(bal) - 1;
                if (tid == 0) g_pos[b * NBOX + count] = base + o;
                count++;
                bal &= bal - 1;
            }
        }
    }
}

__global__ void gather_kernel(const float* __restrict__ emb) {
    int r = blockIdx.x;
    int b = r / NBOX;
    const float* src = emb + ((long)b * SEQ + g_pos[r]) * DIM;
    for (int i = threadIdx.x; i < DIM; i += blockDim.x) g_qtok[(long)r * DIM + i] = src[i];
}

__global__ void scatter_kernel(float* __restrict__ out) {
    int r = blockIdx.x;
    int b = r / NBOX;
    float* dst = out + ((long)b * SEQ + g_pos[r]) * DIM;
    for (int i = threadIdx.x; i < DIM; i += blockDim.x) dst[i] = g_rows[(long)r * DIM + i];
}

// ------------------------- skinny TMA tf32 mma GEMM (TB, 2-stage) ------------
__global__ __launch_bounds__(TPBS) void skinny_tma(
    const __grid_constant__ CUtensorMap mapA,
    const __grid_constant__ CUtensorMap mapW,
    int zxA, int zyW,
    float* __restrict__ P, int N, int K, int SK)
{
    __shared__ __align__(1024) unsigned char sm[2 * 12288];
    __shared__ unsigned long long mbar[2];

    const int z = blockIdx.z, s = blockIdx.y;
    const int n0 = blockIdx.x * 64;
    const int Kc = K / SK;
    const int kBeg = s * Kc;
    const int nT = Kc / 32;

    const int tid  = threadIdx.x;
    const int wid  = tid >> 5;
    const int lane = tid & 31;
    const int grp  = lane >> 2;
    const int th   = lane & 3;

    unsigned smU = (unsigned)__cvta_generic_to_shared(sm);
    unsigned mbU = (unsigned)__cvta_generic_to_shared(mbar);

    if (tid == 0) {
        asm volatile("mbarrier.init.shared.b64 [%0], 1;" :: "r"(mbU) : "memory");
        asm volatile("mbarrier.init.shared.b64 [%0], 1;" :: "r"(mbU + 8) : "memory");
    }
    __syncthreads();

    auto issue = [&](int t, int buf) {
        unsigned mb = mbU + buf * 8;
        asm volatile("mbarrier.arrive.expect_tx.shared.b64 _, [%0], %1;"
                     :: "r"(mb), "r"(11264u) : "memory");
        int x = kBeg + t * 32;
        unsigned aA = smU + buf * 12288;
        unsigned aB = aA + 4096;
        asm volatile(
            "cp.async.bulk.tensor.2d.shared::cta.global.tile.mbarrier::complete_tx::bytes "
            "[%0], [%1, {%2, %3}], [%4];"
            :: "r"(aA), "l"(&mapA), "r"(zxA * z + x), "r"(0), "r"(mb) : "memory");
        asm volatile(
            "cp.async.bulk.tensor.2d.shared::cta.global.tile.mbarrier::complete_tx::bytes "
            "[%0], [%1, {%2, %3}], [%4];"
            :: "r"(aB), "l"(&mapW), "r"(x), "r"(zyW * z + n0), "r"(mb) : "memory");
    };

    if (tid == 0) { issue(0, 0); issue(1, 1); }

    float c[2][2][4];
#pragma unroll
    for (int i = 0; i < 2; i++)
#pragma unroll
        for (int j = 0; j < 2; j++)
#pragma unroll
            for (int r = 0; r < 4; r++) c[i][j][r] = 0.f;

    int ph0 = 0, ph1 = 0;
    const unsigned cx = (unsigned)(grp << 4);

    for (int t = 0; t < nT; t++) {
        const int buf = t & 1;
        if (buf == 0) { mbar_wait(mbU, ph0); ph0 ^= 1; }
        else          { mbar_wait(mbU + 8, ph1); ph1 ^= 1; }

        const unsigned char* base = sm + buf * 12288;
        const unsigned char* aT = base;
        const unsigned char* bT = base + 4096;

#pragma unroll
        for (int q = 0; q < 32; q += 8) {
            unsigned c0 = ((unsigned)((q + th) * 4)) ^ cx;
            unsigned c1 = ((unsigned)((q + th + 4) * 4)) ^ cx;
            unsigned a[2][4], b[2][2];
#pragma unroll
            for (int mt = 0; mt < 2; mt++) {
                int r = mt * 16 + grp;
                a[mt][0] = *(const unsigned*)(aT + r * 128 + c0);
                a[mt][1] = *(const unsigned*)(aT + (r + 8) * 128 + c0);
                a[mt][2] = *(const unsigned*)(aT + r * 128 + c1);
                a[mt][3] = *(const unsigned*)(aT + (r + 8) * 128 + c1);
            }
#pragma unroll
            for (int fn = 0; fn < 2; fn++) {
                int col = wid * 16 + fn * 8 + grp;
                b[fn][0] = *(const unsigned*)(bT + col * 128 + c0);
                b[fn][1] = *(const unsigned*)(bT + col * 128 + c1);
            }
#pragma unroll
            for (int mt = 0; mt < 2; mt++)
#pragma unroll
                for (int fn = 0; fn < 2; fn++) {
                    asm volatile(
                        "mma.sync.aligned.m16n8k8.row.col.f32.tf32.tf32.f32 "
                        "{%0,%1,%2,%3}, {%4,%5,%6,%7}, {%8,%9}, {%0,%1,%2,%3};"
                        : "+f"(c[mt][fn][0]), "+f"(c[mt][fn][1]),
                          "+f"(c[mt][fn][2]), "+f"(c[mt][fn][3])
                        : "r"(a[mt][0]), "r"(a[mt][1]), "r"(a[mt][2]), "r"(a[mt][3]),
                          "r"(b[fn][0]), "r"(b[fn][1]));
                }
        }
        __syncthreads();
        if (t + 2 < nT && tid == 0) issue(t + 2, buf);
    }

    long base2 = (long)(z * SK + s) * NTOK * N;
#pragma unroll
    for (int mt = 0; mt < 2; mt++) {
        int r0 = mt * 16 + grp;
#pragma unroll
        for (int fn = 0; fn < 2; fn++) {
            int col = n0 + wid * 16 + fn * 8 + th * 2;
            *reinterpret_cast<float2*>(&P[base2 + (long)r0 * N + col]) =
                make_float2(c[mt][fn][0], c[mt][fn][1]);
            if (mt == 0)
                *reinterpret_cast<float2*>(&P[base2 + (long)(r0 + 8) * N + col]) =
                    make_float2(c[mt][fn][2], c[mt][fn][3]);
        }
    }
}

// ------------------------- skinny cp.async tf32 mma GEMM (NN) ----------------
template<bool TB>
__global__ __launch_bounds__(TPBS) void skinny_mma(
    const float* __restrict__ A, int lda, long Az,
    const float* __restrict__ W, int ldw, long Wz,
    float* __restrict__ P, int N, int K, int SK,
    long zOut, long sOut, int ldcOut)
{
    __shared__ float smem[2][SSTG];
    const int z = blockIdx.z, s = blockIdx.y;
    const int n0 = blockIdx.x * 64;
    const int Kc = K / SK;
    const int kBeg = s * Kc;
    A += (long)z * Az;
    W += (long)z * Wz;

    const int tid  = threadIdx.x;
    const int wid  = tid >> 5;
    const int lane = tid & 31;
    const int grp  = lane >> 2;
    const int th   = lane & 3;

    auto load_tile = [&](int t, int buf) {
        float* As = smem[buf];
        float* Bp = smem[buf] + 1152;
        const int k0 = kBeg + t * 32;
#pragma unroll
        for (int it = 0; it < 2; it++) {
            int idx = tid + it * TPBS;
            int m = idx >> 3, kc = idx & 7;
            cp16(&As[m * 36 + kc * 4], A + (long)m * lda + k0 + kc * 4, m < NTOK);
        }
        if (TB) {
#pragma unroll
            for (int it = 0; it < 4; it++) {
                int idx = tid + it * TPBS;
                int nn = idx >> 3, kc = idx & 7;
                cp16(&Bp[nn * 36 + kc * 4],
                     W + (long)(n0 + nn) * ldw + k0 + kc * 4, n0 + nn < N);
            }
        } else {
#pragma unroll
            for (int it = 0; it < 4; it++) {
                int idx = tid + it * TPBS;
                int kk = idx >> 4, nc = idx & 15;
                cp16(&Bp[kk * 72 + nc * 4],
                     W + (long)(k0 + kk) * ldw + n0 + nc * 4, n0 + nc * 4 < N);
            }
        }
        cp_commit();
    };

    float c[2][2][4];
#pragma unroll
    for (int i = 0; i < 2; i++)
#pragma unroll
        for (int j = 0; j < 2; j++)
#pragma unroll
            for (int r = 0; r < 4; r++) c[i][j][r] = 0.f;

    const int nT = Kc / 32;
    load_tile(0, 0);
    for (int t = 0; t < nT; t++) {
        const int buf = t & 1;
        if (t + 1 < nT) { load_tile(t + 1, buf ^ 1); cp_wait<1>(); }
        else            { cp_wait<0>(); }
        __syncthreads();

        const float* As = smem[buf];
        const float* Bp = smem[buf] + 1152;

#pragma unroll
        for (int q = 0; q < 32; q += 8) {
            unsigned a[2][4], b[2][2];
#pragma unroll
            for (int mt = 0; mt < 2; mt++) {
                int row = mt * 16 + grp;
                const unsigned* ap  = reinterpret_cast<const unsigned*>(&As[row * 36 + q + th]);
                const unsigned* ap8 = reinterpret_cast<const unsigned*>(&As[(row + 8) * 36 + q + th]);
                a[mt][0] = ap[0];
                a[mt][1] = ap8[0];
                a[mt][2] = ap[4];
                a[mt][3] = ap8[4];
            }
#pragma unroll
            for (int fn = 0; fn < 2; fn++) {
                int col = wid * 16 + fn * 8 + grp;
                if (TB) {
                    const unsigned* bp = reinterpret_cast<const unsigned*>(&Bp[col * 36 + q + th]);
                    b[fn][0] = bp[0];
                    b[fn][1] = bp[4];
                } else {
                    b[fn][0] = reinterpret_cast<const unsigned*>(&Bp[(q + th) * 72 + col])[0];
                    b[fn][1] = reinterpret_cast<const unsigned*>(&Bp[(q + th + 4) * 72 + col])[0];
                }
            }
#pragma unroll
            for (int mt = 0; mt < 2; mt++)
#pragma unroll
                for (int fn = 0; fn < 2; fn++) {
                    asm volatile(
                        "mma.sync.aligned.m16n8k8.row.col.f32.tf32.tf32.f32 "
                        "{%0,%1,%2,%3}, {%4,%5,%6,%7}, {%8,%9}, {%0,%1,%2,%3};"
                        : "+f"(c[mt][fn][0]), "+f"(c[mt][fn][1]),
                          "+f"(c[mt][fn][2]), "+f"(c[mt][fn][3])
                        : "r"(a[mt][0]), "r"(a[mt][1]), "r"(a[mt][2]), "r"(a[mt][3]),
                          "r"(b[fn][0]), "r"(b[fn][1]));
                }
        }
        __syncthreads();
    }

    long base = (long)z * zOut + (long)s * sOut;
#pragma unroll
    for (int mt = 0; mt < 2; mt++) {
        int r0 = mt * 16 + grp;
#pragma unroll
        for (int fn = 0; fn < 2; fn++) {
            int col = n0 + wid * 16 + fn * 8 + th * 2;
            if (col < N) {
                *reinterpret_cast<float2*>(&P[base + (long)r0 * ldcOut + col]) =
                    make_float2(c[mt][fn][0], c[mt][fn][1]);
                if (mt == 0)
                    *reinterpret_cast<float2*>(&P[base + (long)(r0 + 8) * ldcOut + col]) =
                        make_float2(c[mt][fn][2], c[mt][fn][3]);
            }
        }
    }
}

// ------------------------- big tf32 mma GEMM (M=96, 3-stage pipeline) --------
template<bool TB>
__global__ __launch_bounds__(TPB) void mma_gemm(
    const float* __restrict__ A, long Az,
    const float* __restrict__ B, long Bz,
    float* __restrict__ P, int N, int K, int SK,
    const int* __restrict__ patchStart)
{
    extern __shared__ float smem[];
    const int z = blockIdx.z, s = blockIdx.y;
    const int n0 = blockIdx.x * 64;
    const int kLen = K / SK;
    const int kBeg = s * kLen;
    A += (long)z * Az;
    B += (long)z * Bz + (long)patchStart[z] * DIM;

    const int tid  = threadIdx.x;
    const int wid  = tid >> 5;
    const int lane = tid & 31;
    const int grp  = lane >> 2;
    const int th   = lane & 3;
    const int warpM = wid >> 2;
    const int warpN = wid & 3;

    auto load_tile = [&](int t, int buf) {
        float* As = smem + buf * STG;
        float* Bp = smem + buf * STG + 3456;
        const int k0 = kBeg + t * 32;
#pragma unroll
        for (int it = 0; it < 3; it++) {
            int idx = tid + it * TPB;
            int m = idx >> 3, kc = idx & 7;
            cp16(&As[m * 36 + kc * 4], A + (long)m * K + k0 + kc * 4, true);
        }
        if (TB) {
#pragma unroll
            for (int it = 0; it < 2; it++) {
                int idx = tid + it * TPB;
                int nn = idx >> 3, kc = idx & 7;
                cp16(&Bp[nn * 36 + kc * 4], B + (long)(n0 + nn) * DIM + k0 + kc * 4, true);
            }
        } else {
#pragma unroll
            for (int it = 0; it < 2; it++) {
                int idx = tid + it * TPB;
                int kk = idx >> 4, nc = idx & 15;
                cp16(&Bp[kk * 72 + nc * 4], B + (long)(k0 + kk) * DIM + n0 + nc * 4, true);
            }
        }
        cp_commit();
    };

    float c[3][2][4];
#pragma unroll
    for (int i = 0; i < 3; i++)
#pragma unroll
        for (int j = 0; j < 2; j++)
#pragma unroll
            for (int r = 0; r < 4; r++) c[i][j][r] = 0.f;

    const int nT = kLen / 32;
    load_tile(0, 0);
    if (nT > 1) load_tile(1, 1);
    for (int t = 0; t < nT; t++) {
        const int buf = t % 3;
        if (t + 2 < nT) load_tile(t + 2, (t + 2) % 3);
        int ahead = nT - 1 - t;
        if (ahead >= 2)      cp_wait<2>();
        else if (ahead == 1) cp_wait<1>();
        else                 cp_wait<0>();
        __syncthreads();

        const float* As = smem + buf * STG;
        const float* Bp = smem + buf * STG + 3456;

#pragma unroll
        for (int q = 0; q < 32; q += 8) {
            unsigned a[3][4], b[2][2];
#pragma unroll
            for (int fr = 0; fr < 3; fr++) {
                int row = warpM * 48 + fr * 16 + grp;
                const unsigned* ap  = reinterpret_cast<const unsigned*>(&As[row * 36 + q + th]);
                const unsigned* ap8 = reinterpret_cast<const unsigned*>(&As[(row + 8) * 36 + q + th]);
                a[fr][0] = ap[0];
                a[fr][1] = ap8[0];
                a[fr][2] = ap[4];
                a[fr][3] = ap8[4];
            }
#pragma unroll
            for (int fn = 0; fn < 2; fn++) {
                int col = warpN * 16 + fn * 8 + grp;
                if (TB) {
                    const unsigned* bp = reinterpret_cast<const unsigned*>(&Bp[col * 36 + q + th]);
                    b[fn][0] = bp[0];
                    b[fn][1] = bp[4];
                } else {
                    b[fn][0] = reinterpret_cast<const unsigned*>(&Bp[(q + th) * 72 + col])[0];
                    b[fn][1] = reinterpret_cast<const unsigned*>(&Bp[(q + th + 4) * 72 + col])[0];
                }
            }
#pragma unroll
            for (int fr = 0; fr < 3; fr++)
#pragma unroll
                for (int fn = 0; fn < 2; fn++) {
                    asm volatile(
                        "mma.sync.aligned.m16n8k8.row.col.f32.tf32.tf32.f32 "
                        "{%0,%1,%2,%3}, {%4,%5,%6,%7}, {%8,%9}, {%0,%1,%2,%3};"
                        : "+f"(c[fr][fn][0]), "+f"(c[fr][fn][1]),
                          "+f"(c[fr][fn][2]), "+f"(c[fr][fn][3])
                        : "r"(a[fr][0]), "r"(a[fr][1]), "r"(a[fr][2]), "r"(a[fr][3]),
                          "r"(b[fn][0]), "r"(b[fn][1]));
                }
        }
        __syncthreads();
    }

    long base = (long)(z * SK + s) * 96 * N;
#pragma unroll
    for (int fr = 0; fr < 3; fr++) {
        int r0 = warpM * 48 + fr * 16 + grp;
#pragma unroll
        for (int fn = 0; fn < 2; fn++) {
            int col = n0 + warpN * 16 + fn * 8 + th * 2;
            *reinterpret_cast<float2*>(&P[base + (long)r0 * N + col]) =
                make_float2(c[fr][fn][0], c[fr][fn][1]);
            *reinterpret_cast<float2*>(&P[base + (long)(r0 + 8) * N + col]) =
                make_float2(c[fr][fn][2], c[fr][fn][3]);
        }
    }
}

// --------- combine: two-phase (batch loads into array, then sum), float4 -----
template<int SK>
__global__ void combine_kernel(const float* __restrict__ P,
                               float* __restrict__ C, int ldc, long Cz, int M, int N,
                               const float* __restrict__ bias, long biasZ,
                               const float* __restrict__ resid, long residZ,
                               float scale, int act, int total4) {
    int idx = blockIdx.x * blockDim.x + threadIdx.x;
    if (idx >= total4) return;
    int n4 = N >> 2;
    int n = (idx % n4) << 2;
    int t = idx / n4;
    int m = t % M;
    int z = t / M;

    float4 p[SK];
#pragma unroll
    for (int s = 0; s < SK; s++)
        p[s] = *reinterpret_cast<const float4*>(
            &P[((long)(z * SK + s) * M + m) * N + n]);

    float4 v = p[0];
#pragma unroll
    for (int s = 1; s < SK; s++) {
        v.x += p[s].x; v.y += p[s].y; v.z += p[s].z; v.w += p[s].w;
    }
    if (bias) {
        float4 b = *reinterpret_cast<const float4*>(&bias[z * biasZ + n]);
        v.x += b.x; v.y += b.y; v.z += b.z; v.w += b.w;
    }
    v.x *= scale; v.y *= scale; v.z *= scale; v.w *= scale;
    if (act) {
        v.x = v.x * normcdff(v.x);
        v.y = v.y * normcdff(v.y);
        v.z = v.z * normcdff(v.z);
        v.w = v.w * normcdff(v.w);
    }
    if (resid) {
        float4 r = *reinterpret_cast<const float4*>(
            &resid[z * residZ + (long)m * ldc + n]);
        v.x += r.x; v.y += r.y; v.z += r.z; v.w += r.w;
    }
    *reinterpret_cast<float4*>(&C[z * Cz + (long)m * ldc + n]) = v;
}

// ------------------------- masked softmax (fuses score split-K reduce) -------
__global__ void softmax_kernel(const float* __restrict__ P,
                               float* __restrict__ attn,
                               const float* __restrict__ boxes,
                               const int* __restrict__ thw) {
    int blk = blockIdx.x;
    int b = blk / (NBOX * NHD);
    int n = (blk / NHD) % NBOX;
    int h = blk % NHD;
    int m = n * NHD + h;
    int hg = thw[1], wg = thw[2];
    const float* bx = boxes + (long)(b * NBOX + n) * 4;
    float x1 = bx[0], y1 = bx[1], x2 = bx[2], y2 = bx[3];
    int px1 = min(max((int)floorf(x1 * (float)wg), 0), wg - 1);
    int px2 = max(px1 + 1, min((int)floorf(x2 * (float)wg), wg));
    int py1 = min(max((int)floorf(y1 * (float)hg), 0), hg - 1);
    int py2 = max(py1 + 1, min((int)floorf(y2 * (float)hg), hg));

    const float* r0 = P + ((long)(b * 4 + 0) * 96 + m) * NPATCH;
    const float* r1 = P + ((long)(b * 4 + 1) * 96 + m) * NPATCH;
    const float* r2 = P + ((long)(b * 4 + 2) * 96 + m) * NPATCH;
    const float* r3 = P + ((long)(b * 4 + 3) * 96 + m) * NPATCH;
    float* orow = attn + (long)blk * NPATCH;

    __shared__ float sh[NPATCH];
    __shared__ float red[TPB];
    int tid = threadIdx.x;
    int hw = hg * wg;

    float mx = -1e30f;
    for (int i = tid; i < NPATCH; i += TPB) {
        int q = i % hw;
        int rr = q / wg, cc = q % wg;
        bool in = (rr >= py1) && (rr < py2) && (cc >= px1) && (cc < px2);
        float a0 = r0[i], a1 = r1[i], a2 = r2[i], a3 = r3[i];
        float v = in ? ((a0 + a1) + (a2 + a3)) : -1e30f;
        sh[i] = v;
        mx = fmaxf(mx, v);
    }
    red[tid] = mx;
    __syncthreads();
    for (int s = TPB / 2; s > 0; s >>= 1) {
        if (tid < s) red[tid] = fmaxf(red[tid], red[tid + s]);
        __syncthreads();
    }
    float maxv = red[0];
    __syncthreads();

    float sum = 0.f;
    for (int i = tid; i < NPATCH; i += TPB) {
        float e = expf(sh[i] - maxv);
        sh[i] = e;
        sum += e;
    }
    red[tid] = sum;
    __syncthreads();
    for (int s = TPB / 2; s > 0; s >>= 1) {
        if (tid < s) red[tid] += red[tid + s];
        __syncthreads();
    }
    float inv = 1.f / red[0];
    __syncthreads();
    for (int i = tid; i < NPATCH; i += TPB) orow[i] = sh[i] * inv;
}

// ------------------------- layernorm (two-phase partial reduce) --------------
__global__ void ln_fused_kernel(const float* __restrict__ P,
                                const float* __restrict__ bout,
                                const float* __restrict__ gamma,
                                const float* __restrict__ beta) {
    int r = blockIdx.x;
    __shared__ float red[TPB];
    __shared__ float red2[TPB];
    int tid = threadIdx.x;
    float s = 0.f, s2 = 0.f;
    for (int i = tid * 4; i < DIM; i += TPB * 4) {
        float4 p[16];
#pragma unroll
        for (int k = 0; k < 16; k++)
            p[k] = *reinterpret_cast<const float4*>(
                &P[((long)(k * NTOK) + r) * DIM + i]);
        float4 v = *reinterpret_cast<const float4*>(&bout[i]);
        float4 qv = *reinterpret_cast<const float4*>(&g_qtok[(long)r * DIM + i]);
        v.x += qv.x; v.y += qv.y; v.z += qv.z; v.w += qv.w;
#pragma unroll
        for (int k = 0; k < 16; k++) {
            v.x += p[k].x; v.y += p[k].y; v.z += p[k].z; v.w += p[k].w;
        }
        *reinterpret_cast<float4*>(&g_comb[(long)r * DIM + i]) = v;
        s += v.x + v.y + v.z + v.w;
        s2 += v.x * v.x + v.y * v.y + v.z * v.z + v.w * v.w;
    }
    red[tid] = s; red2[tid] = s2;
    __syncthreads();
    for (int st = TPB / 2; st > 0; st >>= 1) {
        if (tid < st) { red[tid] += red[tid + st]; red2[tid] += red2[tid + st]; }
        __syncthreads();
    }
    float mu = red[0] / DIM;
    float var = red2[0] / DIM - mu * mu;
    float inv = rsqrtf(var + 1e-5f);
    for (int i = tid; i < DIM; i += TPB)
        g_ln[(long)r * DIM + i] = (g_comb[(long)r * DIM + i] - mu) * inv * gamma[i] + beta[i];
}

// ------------------------- host tensormap helper -----------------------------
typedef CUresult (*EncodeFn)(
    CUtensorMap*, CUtensorMapDataType, cuuint32_t, void*,
    const cuuint64_t*, const cuuint64_t*, const cuuint32_t*, const cuuint32_t*,
    CUtensorMapInterleave, CUtensorMapSwizzle, CUtensorMapL2promotion,
    CUtensorMapFloatOOBfill);

static void encode_map(EncodeFn fn, CUtensorMap* m, void* ptr,
                       unsigned long long width, unsigned long long height,
                       unsigned long long strideBytes,
                       unsigned boxW, unsigned boxH) {
    cuuint64_t dims[2]    = { width, height };
    cuuint64_t strides[1] = { strideBytes };
    cuuint32_t box[2]     = { boxW, boxH };
    cuuint32_t es[2]      = { 1, 1 };
    fn(m, CU_TENSOR_MAP_DATA_TYPE_FLOAT32, 2, ptr, dims, strides, box, es,
       CU_TENSOR_MAP_INTERLEAVE_NONE, CU_TENSOR_MAP_SWIZZLE_128B,
       CU_TENSOR_MAP_L2_PROMOTION_L2_128B, CU_TENSOR_MAP_FLOAT_OOB_FILL_NONE);
}

// ------------------------- launch --------------------------------------------
extern "C" void kernel_launch(void* const* d_in, const int* in_sizes, int n_in,
                              void* d_out, int out_size) {
    const float*         emb   = (const float*)d_in[0];
    const int*           ids   = (const int*)d_in[1];
    const unsigned char* msk   = (const unsigned char*)d_in[2];
    const float*         boxes = (const float*)d_in[3];
    const int*           thw   = (const int*)d_in[4];
    const int*           tok   = (const int*)d_in[5];
    const float*         Win   = (const float*)d_in[6];
    const float*         bin   = (const float*)d_in[7];
    const float*         Wout  = (const float*)d_in[8];
    const float*         bout  = (const float*)d_in[9];
    const float*         gam   = (const float*)d_in[10];
    const float*         bet   = (const float*)d_in[11];
    const float*         W1    = (const float*)d_in[12];
    const float*         b1    = (const float*)d_in[13];
    const float*         W2    = (const float*)d_in[14];
    const float*         b2    = (const float*)d_in[15];
    float*               out   = (float*)d_out;

    const float* Wq = Win;
    const float* Wk = Win + (long)DIM * DIM;
    const float* Wv = Win + 2L * DIM * DIM;
    const float* bv = bin + 2L * DIM;

    float *qtok, *q, *qk, *scores, *u, *ctx, *ln, *hidden, *rows, *part;
    int *start;
    cudaGetSymbolAddress((void**)&qtok,   g_qtok);
    cudaGetSymbolAddress((void**)&q,      g_q);
    cudaGetSymbolAddress((void**)&qk,     g_qk);
    cudaGetSymbolAddress((void**)&scores, g_scores);
    cudaGetSymbolAddress((void**)&u,      g_u);
    cudaGetSymbolAddress((void**)&ctx,    g_ctx);
    cudaGetSymbolAddress((void**)&ln,     g_ln);
    cudaGetSymbolAddress((void**)&hidden, g_hidden);
    cudaGetSymbolAddress((void**)&rows,   g_rows);
    cudaGetSymbolAddress((void**)&part,   g_part);
    cudaGetSymbolAddress((void**)&start,  g_start);

    cudaFuncSetAttribute(mma_gemm<true>,  cudaFuncAttributeMaxDynamicSharedMemorySize, SMEM_BYTES);
    cudaFuncSetAttribute(mma_gemm<false>, cudaFuncAttributeMaxDynamicSharedMemorySize, SMEM_BYTES);

    // tensormaps for TMA weight streaming
    EncodeFn enc = nullptr;
    cudaGetDriverEntryPoint("cuTensorMapEncodeTiled", (void**)&enc, cudaEnableDefault);
    CUtensorMap mQtok, mU, mCtx, mLn, mHid, mWq, mWv, mWout, mW1, mW2;
    encode_map(enc, &mQtok, qtok,        DIM, NTOK, (unsigned long long)DIM * 4,       32, 24);
    encode_map(enc, &mU,    u,           (unsigned long long)NHD * DIM, NTOK,
                                                    (unsigned long long)NHD * DIM * 4, 32, 24);
    encode_map(enc, &mCtx,  ctx,         DIM, NTOK, (unsigned long long)DIM * 4,       32, 24);
    encode_map(enc, &mLn,   ln,          DIM, NTOK, (unsigned long long)DIM * 4,       32, 24);
    encode_map(enc, &mHid,  hidden,      DFF, NTOK, (unsigned long long)DFF * 4,       32, 24);
    encode_map(enc, &mWq,   (void*)Wq,   DIM, DIM,  (unsigned long long)DIM * 4,       32, 64);
    encode_map(enc, &mWv,   (void*)Wv,   DIM, DIM,  (unsigned long long)DIM * 4,       32, 64);
    encode_map(enc, &mWout, (void*)Wout, DIM, DIM,  (unsigned long long)DIM * 4,       32, 64);
    encode_map(enc, &mW1,   (void*)W1,   DIM, DFF,  (unsigned long long)DIM * 4,       32, 64);
    encode_map(enc, &mW2,   (void*)W2,   DFF, DIM,  (unsigned long long)DFF * 4,       32, 64);

    const float scale = 1.0f / sqrtf((float)DHD);

    // ---- fork: base copy via copy engine on side stream ----
    cudaStream_t s2;
    cudaStreamCreate(&s2);
    cudaEvent_t eFork, eJoin;
    cudaEventCreateWithFlags(&eFork, cudaEventDisableTiming);
    cudaEventCreateWithFlags(&eJoin, cudaEventDisableTiming);
    cudaEventRecord(eFork, 0);
    cudaStreamWaitEvent(s2, eFork, 0);
    cudaMemcpyAsync(out, emb, (size_t)BATCH * SEQ * DIM * sizeof(float),
                    cudaMemcpyDeviceToDevice, s2);
    cudaEventRecord(eJoin, s2);

    // ---- main chain ----
    scan_kernel<<<BATCH, TPB>>>(ids, msk, tok);
    gather_kernel<<<NTOK, TPB>>>(emb);

    // 4. q = (qtok @ Wq^T + bq) * scale   (TMA, SK=16, Kc=224)
    skinny_tma<<<dim3(56, 16, 1), TPBS>>>(mQtok, mWq, 0, 0, part, DIM, DIM, 16);
    combine_kernel<16><<<(NTOK * DIM / 4 + TPB - 1) / TPB, TPB>>>(
        part, q, DIM, 0, NTOK, DIM, bin, 0, nullptr, 0, scale, 0, NTOK * DIM / 4);

    // 5. qk[t,h,:] = q[t,h,:] @ Wk_h   (cp.async NN per head, SK=1, DIRECT write)
    skinny_mma<false><<<dim3(56, 1, NHD), TPBS>>>(q, DIM, DHD, Wk, DIM, (long)DHD * DIM,
                                                  qk, DIM, DHD, 1,
                                                  (long)DIM, 0, NHD * DIM);

    // 6. scores = qk @ patches^T   (SK=4) -> partials consumed by softmax
    mma_gemm<true><<<dim3(NPATCH / 64, 4, BATCH), TPB, SMEM_BYTES>>>(
        qk, (long)96 * DIM, emb, (long)SEQ * DIM,
        part, NPATCH, DIM, 4, start);

    // 7. masked softmax
    softmax_kernel<<<BATCH * NBOX * NHD, TPB>>>(part, scores, boxes, thw);

    // 8. u = attn @ patches   (SK=4)
    mma_gemm<false><<<dim3(DIM / 64, 4, BATCH), TPB, SMEM_BYTES>>>(
        scores, (long)96 * NPATCH, emb, (long)SEQ * DIM,
        part, DIM, NPATCH, 4, start);
    combine_kernel<4><<<(BATCH * 96 * DIM / 4 + TPB - 1) / TPB, TPB>>>(
        part, u, DIM, (long)96 * DIM, 96, DIM,
        nullptr, 0, nullptr, 0, 1.f, 0, BATCH * 96 * DIM / 4);

    // 9. ctx[:, h] = u_h @ Wv_h^T + bv_h   (TMA per head)
    skinny_tma<<<dim3(7, 16, NHD), TPBS>>>(mU, mWv, DIM, DHD, part, DHD, DIM, 16);
    combine_kernel<16><<<(NHD * NTOK * DHD / 4 + TPB - 1) / TPB, TPB>>>(
        part, ctx, DIM, DHD, NTOK, DHD, bv, DHD, nullptr, 0, 1.f, 0,
        NHD * NTOK * DHD / 4);

    // 10. combined partials = ctx @ Wout^T   (TMA, SK=16) -> ln_fused
    skinny_tma<<<dim3(56, 16, 1), TPBS>>>(mCtx, mWout, 0, 0, part, DIM, DIM, 16);

    // 11. layernorm (reduces 16 partials + bout + qtok residual)
    ln_fused_kernel<<<NTOK, TPB>>>(part, bout, gam, bet);

    // 12. hidden = gelu(ln @ W1^T + b1)   (TMA, SK=8, Kc=448)
    skinny_tma<<<dim3(112, 8, 1), TPBS>>>(mLn, mW1, 0, 0, part, DFF, DIM, 8);
    combine_kernel<8><<<(NTOK * DFF / 4 + TPB - 1) / TPB, TPB>>>(
        part, hidden, DFF, 0, NTOK, DFF, b1, 0, nullptr, 0, 1.f, 1, NTOK * DFF / 4);

    // 13. rows = ln + hidden @ W2^T + b2   (TMA, SK=16, Kc=448)
    skinny_tma<<<dim3(56, 16, 1), TPBS>>>(mHid, mW2, 0, 0, part, DIM, DFF, 16);
    combine_kernel<16><<<(NTOK * DIM / 4 + TPB - 1) / TPB, TPB>>>(
        part, rows, DIM, 0, NTOK, DIM, b2, 0, ln, 0, 1.f, 0, NTOK * DIM / 4);

    // ---- join: copy must complete before scatter ----
    cudaStreamWaitEvent(0, eJoin, 0);
    scatter_kernel<<<NTOK, TPB>>>(out);
}